// round 1
// baseline (speedup 1.0000x reference)
#include <cuda_runtime.h>
#include <cuda_bf16.h>
#include <math.h>

// Problem constants
#define BB    2
#define SS    2048
#define DD    2048
#define HQ    32
#define HKV   8
#define DH    64
#define MROWS (BB*SS)          // 4096
#define NQ    (HQ*DH)          // 2048
#define NKV   (HKV*DH)         // 512

// Scratch (allocation-free rule: device globals)
__device__ float g_Q[(size_t)MROWS * NQ];   // 32 MB
__device__ float g_K[(size_t)MROWS * NKV];  // 8 MB
__device__ float g_V[(size_t)MROWS * NKV];  // 8 MB
__device__ float g_C[(size_t)MROWS * NQ];   // 32 MB

// ---------------------------------------------------------------------------
// SGEMM: C[M,N] = A[M,K] * B[K,N], row-major, all dims multiples of tile.
// 128x128 block tile, BK=16, 256 threads, 8x8 per thread.
// ---------------------------------------------------------------------------
#define GBM 128
#define GBN 128
#define GBK 16
#define A_PAD 132   // pad A smem rows: breaks transposed-store conflicts, keeps 16B align

__global__ __launch_bounds__(256) void sgemm_kernel(
    const float* __restrict__ A, const float* __restrict__ B,
    float* __restrict__ C, int M, int N, int K)
{
    __shared__ float As[GBK][A_PAD];  // [k][m]
    __shared__ float Bs[GBK][GBN];    // [k][n]

    const int tid = threadIdx.x;
    const int tx = tid & 15;          // N dim (16)
    const int ty = tid >> 4;          // M dim (16)
    const int bm = blockIdx.y * GBM;
    const int bn = blockIdx.x * GBN;

    const int arow = tid >> 2;          // 0..63
    const int acol = (tid & 3) * 4;     // 0,4,8,12
    const int brow = tid >> 5;          // 0..7
    const int bcol = (tid & 31) * 4;    // 0..124

    float acc[8][8];
#pragma unroll
    for (int i = 0; i < 8; i++)
#pragma unroll
        for (int j = 0; j < 8; j++) acc[i][j] = 0.f;

    for (int k0 = 0; k0 < K; k0 += GBK) {
#pragma unroll
        for (int r = 0; r < 2; r++) {
            int row = arow + r * 64;
            float4 v = *(const float4*)&A[(size_t)(bm + row) * K + k0 + acol];
            As[acol + 0][row] = v.x;
            As[acol + 1][row] = v.y;
            As[acol + 2][row] = v.z;
            As[acol + 3][row] = v.w;
        }
#pragma unroll
        for (int r = 0; r < 2; r++) {
            int row = brow + r * 8;
            *(float4*)&Bs[row][bcol] =
                *(const float4*)&B[(size_t)(k0 + row) * N + bn + bcol];
        }
        __syncthreads();

#pragma unroll
        for (int k = 0; k < GBK; k++) {
            float a[8], bb[8];
            *(float4*)&a[0] = *(const float4*)&As[k][ty * 8];
            *(float4*)&a[4] = *(const float4*)&As[k][ty * 8 + 4];
            *(float4*)&bb[0] = *(const float4*)&Bs[k][tx * 8];
            *(float4*)&bb[4] = *(const float4*)&Bs[k][tx * 8 + 4];
#pragma unroll
            for (int i = 0; i < 8; i++)
#pragma unroll
                for (int j = 0; j < 8; j++)
                    acc[i][j] += a[i] * bb[j];
        }
        __syncthreads();
    }

#pragma unroll
    for (int i = 0; i < 8; i++) {
        size_t base = (size_t)(bm + ty * 8 + i) * N + bn + tx * 8;
        *(float4*)&C[base]     = make_float4(acc[i][0], acc[i][1], acc[i][2], acc[i][3]);
        *(float4*)&C[base + 4] = make_float4(acc[i][4], acc[i][5], acc[i][6], acc[i][7]);
    }
}

// ---------------------------------------------------------------------------
// Flash attention fp32: per block, one (batch, head, 64-row q-tile).
// Online softmax over 32 kv tiles of 64. 256 threads, 4x4 per thread.
// Smem: Qs[d][i], KP (K as [d][j], reused for P as [i][j]), Vs[j][d]; pad 68.
// ---------------------------------------------------------------------------
#define F_PAD 68
#define FLASH_SMEM (3 * 64 * F_PAD * 4)

__global__ __launch_bounds__(256) void flash_kernel(
    const float* __restrict__ Q, const float* __restrict__ K,
    const float* __restrict__ V, float* __restrict__ O)
{
    extern __shared__ float sm[];
    float (*Qs)[F_PAD] = (float(*)[F_PAD])sm;                 // [d][qrow]
    float (*KP)[F_PAD] = (float(*)[F_PAD])(sm + 64 * F_PAD);  // K:[d][j]  then P:[i][j]
    float (*Vs)[F_PAD] = (float(*)[F_PAD])(sm + 2 * 64 * F_PAD); // [j][d]

    const int tid = threadIdx.x;
    const int tx = tid & 15;
    const int ty = tid >> 4;
    const int qb = blockIdx.x;
    const int h  = blockIdx.y;
    const int b  = blockIdx.z;
    const int kvh = h >> 2;                 // NUM_REP = 4
    const int qbase = qb * 64;

    const float* Qbase = Q + (size_t)(b * SS + qbase) * NQ + h * DH;
    const float* Kbase = K + (size_t)b * SS * NKV + kvh * DH;
    const float* Vbase = V + (size_t)b * SS * NKV + kvh * DH;

    // Load Q tile (pre-scaled by 1/sqrt(DH)), transposed into Qs[d][row]
#pragma unroll
    for (int t = 0; t < 4; t++) {
        int idx = tid + t * 256;
        int row = idx >> 4;
        int c4  = (idx & 15) * 4;
        float4 v = *(const float4*)(Qbase + (size_t)row * NQ + c4);
        Qs[c4 + 0][row] = v.x * 0.125f;
        Qs[c4 + 1][row] = v.y * 0.125f;
        Qs[c4 + 2][row] = v.z * 0.125f;
        Qs[c4 + 3][row] = v.w * 0.125f;
    }

    float m[4], l[4], acc[4][4];
#pragma unroll
    for (int i = 0; i < 4; i++) {
        m[i] = -1e30f; l[i] = 0.f;
#pragma unroll
        for (int j = 0; j < 4; j++) acc[i][j] = 0.f;
    }

    for (int kt = 0; kt < SS / 64; kt++) {
        const int kb = kt * 64;
        __syncthreads();   // protect KP/Vs reuse from prev iter (and Qs on iter 0)
#pragma unroll
        for (int t = 0; t < 4; t++) {
            int idx = tid + t * 256;
            int row = idx >> 4;
            int c4  = (idx & 15) * 4;
            float4 kv = *(const float4*)(Kbase + (size_t)(kb + row) * NKV + c4);
            KP[c4 + 0][row] = kv.x;
            KP[c4 + 1][row] = kv.y;
            KP[c4 + 2][row] = kv.z;
            KP[c4 + 3][row] = kv.w;
            *(float4*)&Vs[row][c4] =
                *(const float4*)(Vbase + (size_t)(kb + row) * NKV + c4);
        }
        __syncthreads();

        // S = Qs^T * K  (4x4 per thread)
        float s[4][4];
#pragma unroll
        for (int i = 0; i < 4; i++)
#pragma unroll
            for (int j = 0; j < 4; j++) s[i][j] = 0.f;
#pragma unroll
        for (int d = 0; d < 64; d++) {
            float4 qa = *(const float4*)&Qs[d][ty * 4];
            float4 kb4 = *(const float4*)&KP[d][tx * 4];
            float a[4] = {qa.x, qa.y, qa.z, qa.w};
            float bb[4] = {kb4.x, kb4.y, kb4.z, kb4.w};
#pragma unroll
            for (int i = 0; i < 4; i++)
#pragma unroll
                for (int j = 0; j < 4; j++)
                    s[i][j] += a[i] * bb[j];
        }

        // online softmax (row groups of 16 lanes share a row; width-16 shuffles)
#pragma unroll
        for (int i = 0; i < 4; i++) {
            float mx = fmaxf(fmaxf(s[i][0], s[i][1]), fmaxf(s[i][2], s[i][3]));
#pragma unroll
            for (int o = 8; o > 0; o >>= 1)
                mx = fmaxf(mx, __shfl_xor_sync(0xffffffffu, mx, o, 16));
            float mn = fmaxf(m[i], mx);
            float fac = __expf(m[i] - mn);
            m[i] = mn;
            float ls = 0.f;
#pragma unroll
            for (int j = 0; j < 4; j++) { s[i][j] = __expf(s[i][j] - mn); ls += s[i][j]; }
#pragma unroll
            for (int o = 8; o > 0; o >>= 1)
                ls += __shfl_xor_sync(0xffffffffu, ls, o, 16);
            l[i] = l[i] * fac + ls;
#pragma unroll
            for (int j = 0; j < 4; j++) acc[i][j] *= fac;
        }

        __syncthreads();   // everyone done reading KP as K
#pragma unroll
        for (int i = 0; i < 4; i++)
            *(float4*)&KP[ty * 4 + i][tx * 4] =
                make_float4(s[i][0], s[i][1], s[i][2], s[i][3]);
        __syncthreads();

        // O += P * V
#pragma unroll
        for (int j2 = 0; j2 < 64; j2++) {
            float4 vv = *(const float4*)&Vs[j2][tx * 4];
            float vr[4] = {vv.x, vv.y, vv.z, vv.w};
            float p[4];
#pragma unroll
            for (int i = 0; i < 4; i++) p[i] = KP[ty * 4 + i][j2];
#pragma unroll
            for (int i = 0; i < 4; i++)
#pragma unroll
                for (int c = 0; c < 4; c++)
                    acc[i][c] += p[i] * vr[c];
        }
    }

#pragma unroll
    for (int i = 0; i < 4; i++) {
        float inv = 1.0f / l[i];
        int row = qbase + ty * 4 + i;
        *(float4*)&O[(size_t)(b * SS + row) * NQ + h * DH + tx * 4] =
            make_float4(acc[i][0] * inv, acc[i][1] * inv,
                        acc[i][2] * inv, acc[i][3] * inv);
    }
}

// ---------------------------------------------------------------------------
// Launch
// ---------------------------------------------------------------------------
extern "C" void kernel_launch(void* const* d_in, const int* in_sizes, int n_in,
                              void* d_out, int out_size)
{
    const float* x  = (const float*)d_in[0];
    const float* Wq = (const float*)d_in[1];
    const float* Wk = (const float*)d_in[2];
    const float* Wv = (const float*)d_in[3];
    const float* Wo = (const float*)d_in[4];
    float* out = (float*)d_out;

    float *Qb, *Kb, *Vb, *Cb;
    cudaGetSymbolAddress((void**)&Qb, g_Q);
    cudaGetSymbolAddress((void**)&Kb, g_K);
    cudaGetSymbolAddress((void**)&Vb, g_V);
    cudaGetSymbolAddress((void**)&Cb, g_C);

    cudaFuncSetAttribute(flash_kernel,
                         cudaFuncAttributeMaxDynamicSharedMemorySize, FLASH_SMEM);

    // Projections: Q = x@Wq, K = x@Wk, V = x@Wv
    sgemm_kernel<<<dim3(NQ / GBN,  MROWS / GBM), 256>>>(x, Wq, Qb, MROWS, NQ,  DD);
    sgemm_kernel<<<dim3(NKV / GBN, MROWS / GBM), 256>>>(x, Wk, Kb, MROWS, NKV, DD);
    sgemm_kernel<<<dim3(NKV / GBN, MROWS / GBM), 256>>>(x, Wv, Vb, MROWS, NKV, DD);

    // Attention (GQA, flash, fp32)
    flash_kernel<<<dim3(SS / 64, HQ, BB), 256, FLASH_SMEM>>>(Qb, Kb, Vb, Cb);

    // Output projection: out = C @ Wo
    sgemm_kernel<<<dim3(DD / GBN, MROWS / GBM), 256>>>(Cb, Wo, out, MROWS, DD, NQ);
}

// round 2
// speedup vs baseline: 1.4200x; 1.4200x over previous
#include <cuda_runtime.h>
#include <cuda_bf16.h>
#include <math.h>
#include <stdint.h>

// Problem constants
#define BB    2
#define SS    2048
#define DD    2048
#define HQ    32
#define HKV   8
#define DH    64
#define MROWS (BB*SS)          // 4096
#define NQ    (HQ*DH)          // 2048
#define NKV   (HKV*DH)         // 512

// ---------------------------------------------------------------------------
// Scratch (allocation-free rule: device globals)
// ---------------------------------------------------------------------------
__device__ float g_Q[(size_t)MROWS * NQ];   // 32 MB
__device__ float g_K[(size_t)MROWS * NKV];  // 8 MB
__device__ float g_V[(size_t)MROWS * NKV];  // 8 MB
__device__ float g_C[(size_t)MROWS * NQ];   // 32 MB

__device__ __nv_bfloat16 g_xh[(size_t)MROWS * DD],  g_xl[(size_t)MROWS * DD];
__device__ __nv_bfloat16 g_Wqh[(size_t)DD * NQ],    g_Wql[(size_t)DD * NQ];
__device__ __nv_bfloat16 g_Wkh[(size_t)DD * NKV],   g_Wkl[(size_t)DD * NKV];
__device__ __nv_bfloat16 g_Wvh[(size_t)DD * NKV],   g_Wvl[(size_t)DD * NKV];
__device__ __nv_bfloat16 g_Woh[(size_t)NQ * DD],    g_Wol[(size_t)NQ * DD];
__device__ __nv_bfloat16 g_Ch[(size_t)MROWS * NQ],  g_Cl[(size_t)MROWS * NQ];

// ---------------------------------------------------------------------------
// fp32 -> bf16 hi/lo split (memory bound, trivial)
// ---------------------------------------------------------------------------
__global__ __launch_bounds__(256) void split_kernel(
    const float4* __restrict__ in, uint2* __restrict__ hi,
    uint2* __restrict__ lo, int n4)
{
    for (int i = blockIdx.x * blockDim.x + threadIdx.x; i < n4;
         i += gridDim.x * blockDim.x) {
        float4 v = in[i];
        float f[4] = {v.x, v.y, v.z, v.w};
        __nv_bfloat16 h[4], l[4];
#pragma unroll
        for (int j = 0; j < 4; j++) {
            h[j] = __float2bfloat16(f[j]);
            l[j] = __float2bfloat16(f[j] - __bfloat162float(h[j]));
        }
        hi[i] = *(uint2*)h;
        lo[i] = *(uint2*)l;
    }
}

// ---------------------------------------------------------------------------
// MMA helpers (mma.sync m16n8k16 bf16, fp32 accum)
// ---------------------------------------------------------------------------
__device__ __forceinline__ uint32_t sptr(const void* p) {
    return (uint32_t)__cvta_generic_to_shared(p);
}
__device__ __forceinline__ void ldsm_x4(uint32_t* r, uint32_t a) {
    asm volatile("ldmatrix.sync.aligned.m8n8.x4.shared.b16 {%0,%1,%2,%3}, [%4];"
        : "=r"(r[0]), "=r"(r[1]), "=r"(r[2]), "=r"(r[3]) : "r"(a));
}
__device__ __forceinline__ void ldsm_x2t(uint32_t* r, uint32_t a) {
    asm volatile("ldmatrix.sync.aligned.m8n8.x2.trans.shared.b16 {%0,%1}, [%2];"
        : "=r"(r[0]), "=r"(r[1]) : "r"(a));
}
__device__ __forceinline__ void mma16816(float* c, const uint32_t* a, const uint32_t* b) {
    asm volatile(
        "mma.sync.aligned.m16n8k16.row.col.f32.bf16.bf16.f32 "
        "{%0,%1,%2,%3}, {%4,%5,%6,%7}, {%8,%9}, {%0,%1,%2,%3};"
        : "+f"(c[0]), "+f"(c[1]), "+f"(c[2]), "+f"(c[3])
        : "r"(a[0]), "r"(a[1]), "r"(a[2]), "r"(a[3]), "r"(b[0]), "r"(b[1]));
}

// ---------------------------------------------------------------------------
// bf16x3 GEMM: C[M,N] = (Ah+Al) @ (Bh+Bl)  (dropping Al@Bl term)
// 128x128 block tile, BK=32, 256 threads (8 warps, 2x4), warp tile 64x32.
// ---------------------------------------------------------------------------
#define TBM 128
#define TBN 128
#define TBK 32
#define APAD 48    // 96B rows: 16B aligned for ldmatrix (2-way conflict, OK)
#define BPAD 136   // 272B rows: 16B aligned, conflict-free

__global__ __launch_bounds__(256) void mma_gemm(
    const __nv_bfloat16* __restrict__ Ah, const __nv_bfloat16* __restrict__ Al,
    const __nv_bfloat16* __restrict__ Bh, const __nv_bfloat16* __restrict__ Bl,
    float* __restrict__ C, int M, int N, int K)
{
    __shared__ __nv_bfloat16 sA[2][TBM][APAD];
    __shared__ __nv_bfloat16 sB[2][TBK][BPAD];

    const int tid  = threadIdx.x;
    const int lane = tid & 31;
    const int warp = tid >> 5;
    const int wm = warp >> 2;     // 0..1
    const int wn = warp & 3;      // 0..3
    const int bm = blockIdx.y * TBM;
    const int bn = blockIdx.x * TBN;

    const int arow = tid >> 3;          // 0..31 (x4 passes)
    const int ak   = (tid & 7) * 4;
    const int brow = tid >> 4;          // 0..15 (x2 passes)
    const int bn8  = (tid & 15) * 8;

    float acc[4][4][4];
#pragma unroll
    for (int mi = 0; mi < 4; mi++)
#pragma unroll
        for (int nj = 0; nj < 4; nj++)
#pragma unroll
            for (int v = 0; v < 4; v++) acc[mi][nj][v] = 0.f;

    for (int k0 = 0; k0 < K; k0 += TBK) {
#pragma unroll
        for (int p = 0; p < 4; p++) {
            int r = arow + p * 32;
            size_t g = (size_t)(bm + r) * K + k0 + ak;
            *(uint2*)&sA[0][r][ak] = *(const uint2*)(Ah + g);
            *(uint2*)&sA[1][r][ak] = *(const uint2*)(Al + g);
        }
#pragma unroll
        for (int p = 0; p < 2; p++) {
            int r = brow + p * 16;
            size_t g = (size_t)(k0 + r) * N + bn + bn8;
            *(uint4*)&sB[0][r][bn8] = *(const uint4*)(Bh + g);
            *(uint4*)&sB[1][r][bn8] = *(const uint4*)(Bl + g);
        }
        __syncthreads();

#pragma unroll
        for (int kk = 0; kk < TBK; kk += 16) {
            uint32_t ah[4][4], al[4][4], bh[4][2], bl[4][2];
#pragma unroll
            for (int mi = 0; mi < 4; mi++) {
                int row = wm * 64 + mi * 16 + (lane & 15);
                int col = kk + (lane >> 4) * 8;
                ldsm_x4(ah[mi], sptr(&sA[0][row][col]));
                ldsm_x4(al[mi], sptr(&sA[1][row][col]));
            }
#pragma unroll
            for (int nj = 0; nj < 4; nj++) {
                int r = kk + (lane & 15);
                int c = wn * 32 + nj * 8;
                ldsm_x2t(bh[nj], sptr(&sB[0][r][c]));
                ldsm_x2t(bl[nj], sptr(&sB[1][r][c]));
            }
#pragma unroll
            for (int mi = 0; mi < 4; mi++)
#pragma unroll
                for (int nj = 0; nj < 4; nj++) {
                    mma16816(acc[mi][nj], ah[mi], bh[nj]);
                    mma16816(acc[mi][nj], ah[mi], bl[nj]);
                    mma16816(acc[mi][nj], al[mi], bh[nj]);
                }
        }
        __syncthreads();
    }

#pragma unroll
    for (int mi = 0; mi < 4; mi++)
#pragma unroll
        for (int nj = 0; nj < 4; nj++) {
            int row = bm + wm * 64 + mi * 16 + (lane >> 2);
            int col = bn + wn * 32 + nj * 8 + (lane & 3) * 2;
            *(float2*)&C[(size_t)row * N + col] =
                make_float2(acc[mi][nj][0], acc[mi][nj][1]);
            *(float2*)&C[(size_t)(row + 8) * N + col] =
                make_float2(acc[mi][nj][2], acc[mi][nj][3]);
        }
}

// ---------------------------------------------------------------------------
// Flash attention fp32 (unchanged from R0 — converted to mma next round)
// ---------------------------------------------------------------------------
#define F_PAD 68
#define FLASH_SMEM (3 * 64 * F_PAD * 4)

__global__ __launch_bounds__(256) void flash_kernel(
    const float* __restrict__ Q, const float* __restrict__ K,
    const float* __restrict__ V, float* __restrict__ O)
{
    extern __shared__ float sm[];
    float (*Qs)[F_PAD] = (float(*)[F_PAD])sm;
    float (*KP)[F_PAD] = (float(*)[F_PAD])(sm + 64 * F_PAD);
    float (*Vs)[F_PAD] = (float(*)[F_PAD])(sm + 2 * 64 * F_PAD);

    const int tid = threadIdx.x;
    const int tx = tid & 15;
    const int ty = tid >> 4;
    const int qb = blockIdx.x;
    const int h  = blockIdx.y;
    const int b  = blockIdx.z;
    const int kvh = h >> 2;
    const int qbase = qb * 64;

    const float* Qbase = Q + (size_t)(b * SS + qbase) * NQ + h * DH;
    const float* Kbase = K + (size_t)b * SS * NKV + kvh * DH;
    const float* Vbase = V + (size_t)b * SS * NKV + kvh * DH;

#pragma unroll
    for (int t = 0; t < 4; t++) {
        int idx = tid + t * 256;
        int row = idx >> 4;
        int c4  = (idx & 15) * 4;
        float4 v = *(const float4*)(Qbase + (size_t)row * NQ + c4);
        Qs[c4 + 0][row] = v.x * 0.125f;
        Qs[c4 + 1][row] = v.y * 0.125f;
        Qs[c4 + 2][row] = v.z * 0.125f;
        Qs[c4 + 3][row] = v.w * 0.125f;
    }

    float m[4], l[4], acc[4][4];
#pragma unroll
    for (int i = 0; i < 4; i++) {
        m[i] = -1e30f; l[i] = 0.f;
#pragma unroll
        for (int j = 0; j < 4; j++) acc[i][j] = 0.f;
    }

    for (int kt = 0; kt < SS / 64; kt++) {
        const int kb = kt * 64;
        __syncthreads();
#pragma unroll
        for (int t = 0; t < 4; t++) {
            int idx = tid + t * 256;
            int row = idx >> 4;
            int c4  = (idx & 15) * 4;
            float4 kv = *(const float4*)(Kbase + (size_t)(kb + row) * NKV + c4);
            KP[c4 + 0][row] = kv.x;
            KP[c4 + 1][row] = kv.y;
            KP[c4 + 2][row] = kv.z;
            KP[c4 + 3][row] = kv.w;
            *(float4*)&Vs[row][c4] =
                *(const float4*)(Vbase + (size_t)(kb + row) * NKV + c4);
        }
        __syncthreads();

        float s[4][4];
#pragma unroll
        for (int i = 0; i < 4; i++)
#pragma unroll
            for (int j = 0; j < 4; j++) s[i][j] = 0.f;
#pragma unroll
        for (int d = 0; d < 64; d++) {
            float4 qa = *(const float4*)&Qs[d][ty * 4];
            float4 kb4 = *(const float4*)&KP[d][tx * 4];
            float a[4] = {qa.x, qa.y, qa.z, qa.w};
            float bb[4] = {kb4.x, kb4.y, kb4.z, kb4.w};
#pragma unroll
            for (int i = 0; i < 4; i++)
#pragma unroll
                for (int j = 0; j < 4; j++)
                    s[i][j] += a[i] * bb[j];
        }

#pragma unroll
        for (int i = 0; i < 4; i++) {
            float mx = fmaxf(fmaxf(s[i][0], s[i][1]), fmaxf(s[i][2], s[i][3]));
#pragma unroll
            for (int o = 8; o > 0; o >>= 1)
                mx = fmaxf(mx, __shfl_xor_sync(0xffffffffu, mx, o, 16));
            float mn = fmaxf(m[i], mx);
            float fac = __expf(m[i] - mn);
            m[i] = mn;
            float ls = 0.f;
#pragma unroll
            for (int j = 0; j < 4; j++) { s[i][j] = __expf(s[i][j] - mn); ls += s[i][j]; }
#pragma unroll
            for (int o = 8; o > 0; o >>= 1)
                ls += __shfl_xor_sync(0xffffffffu, ls, o, 16);
            l[i] = l[i] * fac + ls;
#pragma unroll
            for (int j = 0; j < 4; j++) acc[i][j] *= fac;
        }

        __syncthreads();
#pragma unroll
        for (int i = 0; i < 4; i++)
            *(float4*)&KP[ty * 4 + i][tx * 4] =
                make_float4(s[i][0], s[i][1], s[i][2], s[i][3]);
        __syncthreads();

#pragma unroll
        for (int j2 = 0; j2 < 64; j2++) {
            float4 vv = *(const float4*)&Vs[j2][tx * 4];
            float vr[4] = {vv.x, vv.y, vv.z, vv.w};
            float p[4];
#pragma unroll
            for (int i = 0; i < 4; i++) p[i] = KP[ty * 4 + i][j2];
#pragma unroll
            for (int i = 0; i < 4; i++)
#pragma unroll
                for (int c = 0; c < 4; c++)
                    acc[i][c] += p[i] * vr[c];
        }
    }

#pragma unroll
    for (int i = 0; i < 4; i++) {
        float inv = 1.0f / l[i];
        int row = qbase + ty * 4 + i;
        *(float4*)&O[(size_t)(b * SS + row) * NQ + h * DH + tx * 4] =
            make_float4(acc[i][0] * inv, acc[i][1] * inv,
                        acc[i][2] * inv, acc[i][3] * inv);
    }
}

// ---------------------------------------------------------------------------
// Launch
// ---------------------------------------------------------------------------
static void split(const float* src, __nv_bfloat16* h, __nv_bfloat16* l, size_t n)
{
    int n4 = (int)(n / 4);
    int blocks = (n4 + 255) / 256;
    if (blocks > 4096) blocks = 4096;
    split_kernel<<<blocks, 256>>>((const float4*)src, (uint2*)h, (uint2*)l, n4);
}

extern "C" void kernel_launch(void* const* d_in, const int* in_sizes, int n_in,
                              void* d_out, int out_size)
{
    const float* x  = (const float*)d_in[0];
    const float* Wq = (const float*)d_in[1];
    const float* Wk = (const float*)d_in[2];
    const float* Wv = (const float*)d_in[3];
    const float* Wo = (const float*)d_in[4];
    float* out = (float*)d_out;

    float *Qb, *Kb, *Vb, *Cb;
    cudaGetSymbolAddress((void**)&Qb, g_Q);
    cudaGetSymbolAddress((void**)&Kb, g_K);
    cudaGetSymbolAddress((void**)&Vb, g_V);
    cudaGetSymbolAddress((void**)&Cb, g_C);

    __nv_bfloat16 *xh, *xl, *Wqh, *Wql, *Wkh, *Wkl, *Wvh, *Wvl, *Woh, *Wol, *Ch, *Cl;
    cudaGetSymbolAddress((void**)&xh,  g_xh);  cudaGetSymbolAddress((void**)&xl,  g_xl);
    cudaGetSymbolAddress((void**)&Wqh, g_Wqh); cudaGetSymbolAddress((void**)&Wql, g_Wql);
    cudaGetSymbolAddress((void**)&Wkh, g_Wkh); cudaGetSymbolAddress((void**)&Wkl, g_Wkl);
    cudaGetSymbolAddress((void**)&Wvh, g_Wvh); cudaGetSymbolAddress((void**)&Wvl, g_Wvl);
    cudaGetSymbolAddress((void**)&Woh, g_Woh); cudaGetSymbolAddress((void**)&Wol, g_Wol);
    cudaGetSymbolAddress((void**)&Ch,  g_Ch);  cudaGetSymbolAddress((void**)&Cl,  g_Cl);

    cudaFuncSetAttribute(flash_kernel,
                         cudaFuncAttributeMaxDynamicSharedMemorySize, FLASH_SMEM);

    // hi/lo splits of inputs
    split(x,  xh,  xl,  (size_t)MROWS * DD);
    split(Wq, Wqh, Wql, (size_t)DD * NQ);
    split(Wk, Wkh, Wkl, (size_t)DD * NKV);
    split(Wv, Wvh, Wvl, (size_t)DD * NKV);
    split(Wo, Woh, Wol, (size_t)NQ * DD);

    // Projections on tensor cores (bf16x3)
    mma_gemm<<<dim3(NQ / TBN,  MROWS / TBM), 256>>>(xh, xl, Wqh, Wql, Qb, MROWS, NQ,  DD);
    mma_gemm<<<dim3(NKV / TBN, MROWS / TBM), 256>>>(xh, xl, Wkh, Wkl, Kb, MROWS, NKV, DD);
    mma_gemm<<<dim3(NKV / TBN, MROWS / TBM), 256>>>(xh, xl, Wvh, Wvl, Vb, MROWS, NKV, DD);

    // Attention (GQA, flash, fp32)
    flash_kernel<<<dim3(SS / 64, HQ, BB), 256, FLASH_SMEM>>>(Qb, Kb, Vb, Cb);

    // Output projection on tensor cores
    split(Cb, Ch, Cl, (size_t)MROWS * NQ);
    mma_gemm<<<dim3(DD / TBN, MROWS / TBM), 256>>>(Ch, Cl, Woh, Wol, out, MROWS, DD, NQ);
}

// round 4
// speedup vs baseline: 2.5848x; 1.8203x over previous
#include <cuda_runtime.h>
#include <cuda_bf16.h>
#include <math.h>
#include <stdint.h>

// Problem constants
#define BB    2
#define SS    2048
#define DD    2048
#define HQ    32
#define HKV   8
#define DH    64
#define MROWS (BB*SS)          // 4096
#define NQ    (HQ*DH)          // 2048
#define NKV   (HKV*DH)         // 512

// ---------------------------------------------------------------------------
// Scratch (allocation-free rule: device globals). All intermediates bf16 hi/lo.
// ---------------------------------------------------------------------------
__device__ __nv_bfloat16 g_xh[(size_t)MROWS * DD],  g_xl[(size_t)MROWS * DD];
__device__ __nv_bfloat16 g_Wqh[(size_t)DD * NQ],    g_Wql[(size_t)DD * NQ];
__device__ __nv_bfloat16 g_Wkh[(size_t)DD * NKV],   g_Wkl[(size_t)DD * NKV];
__device__ __nv_bfloat16 g_Wvh[(size_t)DD * NKV],   g_Wvl[(size_t)DD * NKV];
__device__ __nv_bfloat16 g_Woh[(size_t)NQ * DD],    g_Wol[(size_t)NQ * DD];
__device__ __nv_bfloat16 g_Qh[(size_t)MROWS * NQ],  g_Ql[(size_t)MROWS * NQ];
__device__ __nv_bfloat16 g_Kh[(size_t)MROWS * NKV], g_Kl[(size_t)MROWS * NKV];
__device__ __nv_bfloat16 g_Vh[(size_t)MROWS * NKV], g_Vl[(size_t)MROWS * NKV];
__device__ __nv_bfloat16 g_Ch[(size_t)MROWS * NQ],  g_Cl[(size_t)MROWS * NQ];

// ---------------------------------------------------------------------------
// helpers
// ---------------------------------------------------------------------------
__device__ __forceinline__ uint32_t sptr(const void* p) {
    return (uint32_t)__cvta_generic_to_shared(p);
}
__device__ __forceinline__ void ldsm_x4(uint32_t* r, uint32_t a) {
    asm volatile("ldmatrix.sync.aligned.m8n8.x4.shared.b16 {%0,%1,%2,%3}, [%4];"
        : "=r"(r[0]), "=r"(r[1]), "=r"(r[2]), "=r"(r[3]) : "r"(a));
}
__device__ __forceinline__ void ldsm_x4t(uint32_t* r, uint32_t a) {
    asm volatile("ldmatrix.sync.aligned.m8n8.x4.trans.shared.b16 {%0,%1,%2,%3}, [%4];"
        : "=r"(r[0]), "=r"(r[1]), "=r"(r[2]), "=r"(r[3]) : "r"(a));
}
__device__ __forceinline__ void ldsm_x2t(uint32_t* r, uint32_t a) {
    asm volatile("ldmatrix.sync.aligned.m8n8.x2.trans.shared.b16 {%0,%1}, [%2];"
        : "=r"(r[0]), "=r"(r[1]) : "r"(a));
}
__device__ __forceinline__ void mma16816(float* c, const uint32_t* a, const uint32_t* b) {
    asm volatile(
        "mma.sync.aligned.m16n8k16.row.col.f32.bf16.bf16.f32 "
        "{%0,%1,%2,%3}, {%4,%5,%6,%7}, {%8,%9}, {%0,%1,%2,%3};"
        : "+f"(c[0]), "+f"(c[1]), "+f"(c[2]), "+f"(c[3])
        : "r"(a[0]), "r"(a[1]), "r"(a[2]), "r"(a[3]), "r"(b[0]), "r"(b[1]));
}
// pack two floats into bf16x2 hi and residual-lo words (low half = first arg)
__device__ __forceinline__ void split2(float a, float b, uint32_t& h, uint32_t& l) {
    __nv_bfloat16 ha = __float2bfloat16(a), hb = __float2bfloat16(b);
    __nv_bfloat16 la = __float2bfloat16(a - __bfloat162float(ha));
    __nv_bfloat16 lb = __float2bfloat16(b - __bfloat162float(hb));
    __nv_bfloat162 hv(ha, hb), lv(la, lb);
    h = *(uint32_t*)&hv; l = *(uint32_t*)&lv;
}

// ---------------------------------------------------------------------------
// fp32 -> bf16 hi/lo split (inputs only)
// ---------------------------------------------------------------------------
__global__ __launch_bounds__(256) void split_kernel(
    const float4* __restrict__ in, uint2* __restrict__ hi,
    uint2* __restrict__ lo, int n4)
{
    for (int i = blockIdx.x * blockDim.x + threadIdx.x; i < n4;
         i += gridDim.x * blockDim.x) {
        float4 v = in[i];
        float f[4] = {v.x, v.y, v.z, v.w};
        __nv_bfloat16 h[4], l[4];
#pragma unroll
        for (int j = 0; j < 4; j++) {
            h[j] = __float2bfloat16(f[j]);
            l[j] = __float2bfloat16(f[j] - __bfloat162float(h[j]));
        }
        hi[i] = *(uint2*)h;
        lo[i] = *(uint2*)l;
    }
}

// ---------------------------------------------------------------------------
// bf16x3 GEMM: 128x128x32, 256 thr, 8 warps (2x4), warp tile 64x32.
// Epilogue: fp32 C, or bf16 hi/lo pair.
// ---------------------------------------------------------------------------
#define TBM 128
#define TBN 128
#define TBK 32
#define APAD 48
#define BPAD 136

template<bool BF16OUT>
__global__ __launch_bounds__(256) void mma_gemm(
    const __nv_bfloat16* __restrict__ Ah, const __nv_bfloat16* __restrict__ Al,
    const __nv_bfloat16* __restrict__ Bh, const __nv_bfloat16* __restrict__ Bl,
    float* __restrict__ C, __nv_bfloat16* __restrict__ Ch,
    __nv_bfloat16* __restrict__ Cl, int M, int N, int K)
{
    __shared__ __nv_bfloat16 sA[2][TBM][APAD];
    __shared__ __nv_bfloat16 sB[2][TBK][BPAD];

    const int tid  = threadIdx.x;
    const int lane = tid & 31;
    const int warp = tid >> 5;
    const int wm = warp >> 2;
    const int wn = warp & 3;
    const int bm = blockIdx.y * TBM;
    const int bn = blockIdx.x * TBN;

    const int arow = tid >> 3;
    const int ak   = (tid & 7) * 4;
    const int brow = tid >> 4;
    const int bn8  = (tid & 15) * 8;

    float acc[4][4][4];
#pragma unroll
    for (int mi = 0; mi < 4; mi++)
#pragma unroll
        for (int nj = 0; nj < 4; nj++)
#pragma unroll
            for (int v = 0; v < 4; v++) acc[mi][nj][v] = 0.f;

    for (int k0 = 0; k0 < K; k0 += TBK) {
#pragma unroll
        for (int p = 0; p < 4; p++) {
            int r = arow + p * 32;
            size_t g = (size_t)(bm + r) * K + k0 + ak;
            *(uint2*)&sA[0][r][ak] = *(const uint2*)(Ah + g);
            *(uint2*)&sA[1][r][ak] = *(const uint2*)(Al + g);
        }
#pragma unroll
        for (int p = 0; p < 2; p++) {
            int r = brow + p * 16;
            size_t g = (size_t)(k0 + r) * N + bn + bn8;
            *(uint4*)&sB[0][r][bn8] = *(const uint4*)(Bh + g);
            *(uint4*)&sB[1][r][bn8] = *(const uint4*)(Bl + g);
        }
        __syncthreads();

#pragma unroll
        for (int kk = 0; kk < TBK; kk += 16) {
            uint32_t ah[4][4], al[4][4], bh[4][2], bl[4][2];
#pragma unroll
            for (int mi = 0; mi < 4; mi++) {
                int row = wm * 64 + mi * 16 + (lane & 15);
                int col = kk + (lane >> 4) * 8;
                ldsm_x4(ah[mi], sptr(&sA[0][row][col]));
                ldsm_x4(al[mi], sptr(&sA[1][row][col]));
            }
#pragma unroll
            for (int nj = 0; nj < 4; nj++) {
                int r = kk + (lane & 15);
                int c = wn * 32 + nj * 8;
                ldsm_x2t(bh[nj], sptr(&sB[0][r][c]));
                ldsm_x2t(bl[nj], sptr(&sB[1][r][c]));
            }
#pragma unroll
            for (int mi = 0; mi < 4; mi++)
#pragma unroll
                for (int nj = 0; nj < 4; nj++) {
                    mma16816(acc[mi][nj], ah[mi], bh[nj]);
                    mma16816(acc[mi][nj], ah[mi], bl[nj]);
                    mma16816(acc[mi][nj], al[mi], bh[nj]);
                }
        }
        __syncthreads();
    }

#pragma unroll
    for (int mi = 0; mi < 4; mi++)
#pragma unroll
        for (int nj = 0; nj < 4; nj++) {
            int row = bm + wm * 64 + mi * 16 + (lane >> 2);
            int col = bn + wn * 32 + nj * 8 + (lane & 3) * 2;
            if (BF16OUT) {
                uint32_t hv, lv;
                split2(acc[mi][nj][0], acc[mi][nj][1], hv, lv);
                *(uint32_t*)&Ch[(size_t)row * N + col] = hv;
                *(uint32_t*)&Cl[(size_t)row * N + col] = lv;
                split2(acc[mi][nj][2], acc[mi][nj][3], hv, lv);
                *(uint32_t*)&Ch[(size_t)(row + 8) * N + col] = hv;
                *(uint32_t*)&Cl[(size_t)(row + 8) * N + col] = lv;
            } else {
                *(float2*)&C[(size_t)row * N + col] =
                    make_float2(acc[mi][nj][0], acc[mi][nj][1]);
                *(float2*)&C[(size_t)(row + 8) * N + col] =
                    make_float2(acc[mi][nj][2], acc[mi][nj][3]);
            }
        }
}

// ---------------------------------------------------------------------------
// Flash attention, bf16x3 mma. Block: 128 q-rows x one (b,h). 8 warps,
// each owns a 16-row band (softmax warp-local). 64-kv tiles, 32 iters.
// ---------------------------------------------------------------------------
#define FP 72   // padded smem row (bf16 elements): 144B rows, ldsm conflict-free
#define FLASH_SMEM ((256*FP + 4*64*FP) * 2)   // 73728 bytes

__global__ __launch_bounds__(256) void flash_mma(
    const __nv_bfloat16* __restrict__ Qh, const __nv_bfloat16* __restrict__ Ql,
    const __nv_bfloat16* __restrict__ Kh, const __nv_bfloat16* __restrict__ Kl,
    const __nv_bfloat16* __restrict__ Vh, const __nv_bfloat16* __restrict__ Vl,
    __nv_bfloat16* __restrict__ Ch, __nv_bfloat16* __restrict__ Cl)
{
    extern __shared__ __nv_bfloat16 smf[];
    __nv_bfloat16* sQh = smf;
    __nv_bfloat16* sQl = smf + 128 * FP;
    __nv_bfloat16* sKh = smf + 256 * FP;
    __nv_bfloat16* sKl = sKh + 64 * FP;
    __nv_bfloat16* sVh = sKl + 64 * FP;
    __nv_bfloat16* sVl = sVh + 64 * FP;

    const int tid = threadIdx.x, lane = tid & 31, warp = tid >> 5;
    const int qb = blockIdx.x, h = blockIdx.y, b = blockIdx.z;
    const int kvh = h >> 2;
    const int qbase = qb * 128;

    // load Q tile (hi/lo)
    {
        int row = tid >> 1;
        int cb  = (tid & 1) * 4;
        size_t g = (size_t)(b * SS + qbase + row) * NQ + h * DH;
#pragma unroll
        for (int c = 0; c < 4; c++) {
            ((uint4*)(sQh + row * FP))[cb + c] = ((const uint4*)(Qh + g))[cb + c];
            ((uint4*)(sQl + row * FP))[cb + c] = ((const uint4*)(Ql + g))[cb + c];
        }
    }

    float o[8][4];
#pragma unroll
    for (int t = 0; t < 8; t++)
#pragma unroll
        for (int v = 0; v < 4; v++) o[t][v] = 0.f;
    float mrow[2] = {-1e30f, -1e30f}, lrow[2] = {0.f, 0.f};

    const int kvrow = tid >> 2;        // 0..63
    const int kvc   = tid & 3;         // u4 cols kvc, kvc+4

    for (int kt = 0; kt < SS / 64; kt++) {
        __syncthreads();
        {
            size_t g = (size_t)(b * SS + kt * 64 + kvrow) * NKV + kvh * DH;
            uint4* dKh = (uint4*)(sKh + kvrow * FP);
            uint4* dKl = (uint4*)(sKl + kvrow * FP);
            uint4* dVh = (uint4*)(sVh + kvrow * FP);
            uint4* dVl = (uint4*)(sVl + kvrow * FP);
            dKh[kvc]     = ((const uint4*)(Kh + g))[kvc];
            dKh[kvc + 4] = ((const uint4*)(Kh + g))[kvc + 4];
            dKl[kvc]     = ((const uint4*)(Kl + g))[kvc];
            dKl[kvc + 4] = ((const uint4*)(Kl + g))[kvc + 4];
            dVh[kvc]     = ((const uint4*)(Vh + g))[kvc];
            dVh[kvc + 4] = ((const uint4*)(Vh + g))[kvc + 4];
            dVl[kvc]     = ((const uint4*)(Vl + g))[kvc];
            dVl[kvc + 4] = ((const uint4*)(Vl + g))[kvc + 4];
        }
        __syncthreads();

        // ---- S = Q K^T (bf16x3), warp band = 16 rows x 64 kv cols ----
        float s[8][4];
#pragma unroll
        for (int t = 0; t < 8; t++)
#pragma unroll
            for (int v = 0; v < 4; v++) s[t][v] = 0.f;

#pragma unroll
        for (int ks = 0; ks < 4; ks++) {
            uint32_t qhf[4], qlf[4];
            uint32_t qa = (warp * 16 + (lane & 15)) * FP + ks * 16 + (lane >> 4) * 8;
            ldsm_x4(qhf, sptr(sQh + qa));
            ldsm_x4(qlf, sptr(sQl + qa));
#pragma unroll
            for (int np = 0; np < 4; np++) {
                uint32_t kh4[4], kl4[4];
                uint32_t ka = (np * 16 + (lane & 7) + ((lane >> 4) << 3)) * FP
                            + ks * 16 + ((lane >> 3) & 1) * 8;
                ldsm_x4(kh4, sptr(sKh + ka));
                ldsm_x4(kl4, sptr(sKl + ka));
                mma16816(s[2*np],   qhf, &kh4[0]);
                mma16816(s[2*np],   qlf, &kh4[0]);
                mma16816(s[2*np],   qhf, &kl4[0]);
                mma16816(s[2*np+1], qhf, &kh4[2]);
                mma16816(s[2*np+1], qlf, &kh4[2]);
                mma16816(s[2*np+1], qhf, &kl4[2]);
            }
        }

        // ---- online softmax (rows lane>>2 and +8, cols across lane&3) ----
        float mx0 = -1e30f, mx1 = -1e30f;
#pragma unroll
        for (int t = 0; t < 8; t++) {
#pragma unroll
            for (int v = 0; v < 4; v++) s[t][v] *= 0.125f;
            mx0 = fmaxf(mx0, fmaxf(s[t][0], s[t][1]));
            mx1 = fmaxf(mx1, fmaxf(s[t][2], s[t][3]));
        }
#pragma unroll
        for (int off = 1; off <= 2; off <<= 1) {
            mx0 = fmaxf(mx0, __shfl_xor_sync(0xffffffffu, mx0, off));
            mx1 = fmaxf(mx1, __shfl_xor_sync(0xffffffffu, mx1, off));
        }
        float mn0 = fmaxf(mrow[0], mx0), mn1 = fmaxf(mrow[1], mx1);
        float fac0 = __expf(mrow[0] - mn0), fac1 = __expf(mrow[1] - mn1);
        mrow[0] = mn0; mrow[1] = mn1;
        float ls0 = 0.f, ls1 = 0.f;
#pragma unroll
        for (int t = 0; t < 8; t++) {
            s[t][0] = __expf(s[t][0] - mn0); ls0 += s[t][0];
            s[t][1] = __expf(s[t][1] - mn0); ls0 += s[t][1];
            s[t][2] = __expf(s[t][2] - mn1); ls1 += s[t][2];
            s[t][3] = __expf(s[t][3] - mn1); ls1 += s[t][3];
        }
#pragma unroll
        for (int off = 1; off <= 2; off <<= 1) {
            ls0 += __shfl_xor_sync(0xffffffffu, ls0, off);
            ls1 += __shfl_xor_sync(0xffffffffu, ls1, off);
        }
        lrow[0] = lrow[0] * fac0 + ls0;
        lrow[1] = lrow[1] * fac1 + ls1;
#pragma unroll
        for (int t = 0; t < 8; t++) {
            o[t][0] *= fac0; o[t][1] *= fac0;
            o[t][2] *= fac1; o[t][3] *= fac1;
        }

        // ---- O += P V (bf16x3), P fragments built from registers ----
#pragma unroll
        for (int j = 0; j < 4; j++) {
            uint32_t pah[4], pal[4];
            split2(s[2*j][0],   s[2*j][1],   pah[0], pal[0]);
            split2(s[2*j][2],   s[2*j][3],   pah[1], pal[1]);
            split2(s[2*j+1][0], s[2*j+1][1], pah[2], pal[2]);
            split2(s[2*j+1][2], s[2*j+1][3], pah[3], pal[3]);
#pragma unroll
            for (int np = 0; np < 4; np++) {
                uint32_t vh4[4], vl4[4];
                uint32_t va = (j * 16 + (lane & 15)) * FP + np * 16 + (lane >> 4) * 8;
                ldsm_x4t(vh4, sptr(sVh + va));
                ldsm_x4t(vl4, sptr(sVl + va));
                mma16816(o[2*np],   pah, &vh4[0]);
                mma16816(o[2*np],   pal, &vh4[0]);
                mma16816(o[2*np],   pah, &vl4[0]);
                mma16816(o[2*np+1], pah, &vh4[2]);
                mma16816(o[2*np+1], pal, &vh4[2]);
                mma16816(o[2*np+1], pah, &vl4[2]);
            }
        }
    }

    // ---- epilogue: normalize and write bf16 hi/lo context ----
    float inv0 = 1.f / lrow[0], inv1 = 1.f / lrow[1];
    int r0 = qbase + warp * 16 + (lane >> 2);
    size_t base0 = (size_t)(b * SS + r0) * NQ + h * DH + (lane & 3) * 2;
    size_t base1 = base0 + (size_t)8 * NQ;
#pragma unroll
    for (int t = 0; t < 8; t++) {
        uint32_t hv, lv;
        split2(o[t][0] * inv0, o[t][1] * inv0, hv, lv);
        *(uint32_t*)&Ch[base0 + t * 8] = hv;
        *(uint32_t*)&Cl[base0 + t * 8] = lv;
        split2(o[t][2] * inv1, o[t][3] * inv1, hv, lv);
        *(uint32_t*)&Ch[base1 + t * 8] = hv;
        *(uint32_t*)&Cl[base1 + t * 8] = lv;
    }
}

// ---------------------------------------------------------------------------
// Launch
// ---------------------------------------------------------------------------
static void split(const float* src, __nv_bfloat16* h, __nv_bfloat16* l, size_t n)
{
    int n4 = (int)(n / 4);
    int blocks = (n4 + 255) / 256;
    if (blocks > 4096) blocks = 4096;
    split_kernel<<<blocks, 256>>>((const float4*)src, (uint2*)h, (uint2*)l, n4);
}

extern "C" void kernel_launch(void* const* d_in, const int* in_sizes, int n_in,
                              void* d_out, int out_size)
{
    const float* x  = (const float*)d_in[0];
    const float* Wq = (const float*)d_in[1];
    const float* Wk = (const float*)d_in[2];
    const float* Wv = (const float*)d_in[3];
    const float* Wo = (const float*)d_in[4];
    float* out = (float*)d_out;

    __nv_bfloat16 *xh, *xl, *Wqh, *Wql, *Wkh, *Wkl, *Wvh, *Wvl, *Woh, *Wol;
    __nv_bfloat16 *Qh, *Ql, *Kh, *Kl, *Vh, *Vl, *Ch, *Cl;
    cudaGetSymbolAddress((void**)&xh,  g_xh);  cudaGetSymbolAddress((void**)&xl,  g_xl);
    cudaGetSymbolAddress((void**)&Wqh, g_Wqh); cudaGetSymbolAddress((void**)&Wql, g_Wql);
    cudaGetSymbolAddress((void**)&Wkh, g_Wkh); cudaGetSymbolAddress((void**)&Wkl, g_Wkl);
    cudaGetSymbolAddress((void**)&Wvh, g_Wvh); cudaGetSymbolAddress((void**)&Wvl, g_Wvl);
    cudaGetSymbolAddress((void**)&Woh, g_Woh); cudaGetSymbolAddress((void**)&Wol, g_Wol);
    cudaGetSymbolAddress((void**)&Qh,  g_Qh);  cudaGetSymbolAddress((void**)&Ql,  g_Ql);
    cudaGetSymbolAddress((void**)&Kh,  g_Kh);  cudaGetSymbolAddress((void**)&Kl,  g_Kl);
    cudaGetSymbolAddress((void**)&Vh,  g_Vh);  cudaGetSymbolAddress((void**)&Vl,  g_Vl);
    cudaGetSymbolAddress((void**)&Ch,  g_Ch);  cudaGetSymbolAddress((void**)&Cl,  g_Cl);

    cudaFuncSetAttribute(flash_mma,
                         cudaFuncAttributeMaxDynamicSharedMemorySize, FLASH_SMEM);

    // split inputs
    split(x,  xh,  xl,  (size_t)MROWS * DD);
    split(Wq, Wqh, Wql, (size_t)DD * NQ);
    split(Wk, Wkh, Wkl, (size_t)DD * NKV);
    split(Wv, Wvh, Wvl, (size_t)DD * NKV);
    split(Wo, Woh, Wol, (size_t)NQ * DD);

    // projections (tensor cores), bf16 hi/lo outputs
    mma_gemm<true><<<dim3(NQ / TBN,  MROWS / TBM), 256>>>(
        xh, xl, Wqh, Wql, nullptr, Qh, Ql, MROWS, NQ,  DD);
    mma_gemm<true><<<dim3(NKV / TBN, MROWS / TBM), 256>>>(
        xh, xl, Wkh, Wkl, nullptr, Kh, Kl, MROWS, NKV, DD);
    mma_gemm<true><<<dim3(NKV / TBN, MROWS / TBM), 256>>>(
        xh, xl, Wvh, Wvl, nullptr, Vh, Vl, MROWS, NKV, DD);

    // attention on tensor cores
    flash_mma<<<dim3(SS / 128, HQ, BB), 256, FLASH_SMEM>>>(
        Qh, Ql, Kh, Kl, Vh, Vl, Ch, Cl);

    // output projection (fp32 out)
    mma_gemm<false><<<dim3(DD / TBN, MROWS / TBM), 256>>>(
        Ch, Cl, Woh, Wol, out, nullptr, nullptr, MROWS, DD, NQ);
}

// round 5
// speedup vs baseline: 2.8755x; 1.1125x over previous
#include <cuda_runtime.h>
#include <cuda_bf16.h>
#include <math.h>
#include <stdint.h>

// Problem constants
#define BB    2
#define SS    2048
#define DD    2048
#define HQ    32
#define HKV   8
#define DH    64
#define MROWS (BB*SS)          // 4096
#define NQ    (HQ*DH)          // 2048
#define NKV   (HKV*DH)         // 512

// ---------------------------------------------------------------------------
// Scratch (allocation-free rule: device globals). All intermediates bf16 hi/lo.
// ---------------------------------------------------------------------------
__device__ __nv_bfloat16 g_xh[(size_t)MROWS * DD],  g_xl[(size_t)MROWS * DD];
__device__ __nv_bfloat16 g_Wqh[(size_t)DD * NQ],    g_Wql[(size_t)DD * NQ];
__device__ __nv_bfloat16 g_Wkh[(size_t)DD * NKV],   g_Wkl[(size_t)DD * NKV];
__device__ __nv_bfloat16 g_Wvh[(size_t)DD * NKV],   g_Wvl[(size_t)DD * NKV];
__device__ __nv_bfloat16 g_Woh[(size_t)NQ * DD],    g_Wol[(size_t)NQ * DD];
__device__ __nv_bfloat16 g_Qh[(size_t)MROWS * NQ],  g_Ql[(size_t)MROWS * NQ];
__device__ __nv_bfloat16 g_Kh[(size_t)MROWS * NKV], g_Kl[(size_t)MROWS * NKV];
__device__ __nv_bfloat16 g_Vh[(size_t)MROWS * NKV], g_Vl[(size_t)MROWS * NKV];
__device__ __nv_bfloat16 g_Ch[(size_t)MROWS * NQ],  g_Cl[(size_t)MROWS * NQ];

// ---------------------------------------------------------------------------
// helpers
// ---------------------------------------------------------------------------
__device__ __forceinline__ uint32_t sptr(const void* p) {
    return (uint32_t)__cvta_generic_to_shared(p);
}
__device__ __forceinline__ void ldsm_x4(uint32_t* r, uint32_t a) {
    asm volatile("ldmatrix.sync.aligned.m8n8.x4.shared.b16 {%0,%1,%2,%3}, [%4];"
        : "=r"(r[0]), "=r"(r[1]), "=r"(r[2]), "=r"(r[3]) : "r"(a));
}
__device__ __forceinline__ void ldsm_x4t(uint32_t* r, uint32_t a) {
    asm volatile("ldmatrix.sync.aligned.m8n8.x4.trans.shared.b16 {%0,%1,%2,%3}, [%4];"
        : "=r"(r[0]), "=r"(r[1]), "=r"(r[2]), "=r"(r[3]) : "r"(a));
}
__device__ __forceinline__ void ldsm_x2t(uint32_t* r, uint32_t a) {
    asm volatile("ldmatrix.sync.aligned.m8n8.x2.trans.shared.b16 {%0,%1}, [%2];"
        : "=r"(r[0]), "=r"(r[1]) : "r"(a));
}
__device__ __forceinline__ void mma16816(float* c, const uint32_t* a, const uint32_t* b) {
    asm volatile(
        "mma.sync.aligned.m16n8k16.row.col.f32.bf16.bf16.f32 "
        "{%0,%1,%2,%3}, {%4,%5,%6,%7}, {%8,%9}, {%0,%1,%2,%3};"
        : "+f"(c[0]), "+f"(c[1]), "+f"(c[2]), "+f"(c[3])
        : "r"(a[0]), "r"(a[1]), "r"(a[2]), "r"(a[3]), "r"(b[0]), "r"(b[1]));
}
__device__ __forceinline__ void split2(float a, float b, uint32_t& h, uint32_t& l) {
    __nv_bfloat16 ha = __float2bfloat16(a), hb = __float2bfloat16(b);
    __nv_bfloat16 la = __float2bfloat16(a - __bfloat162float(ha));
    __nv_bfloat16 lb = __float2bfloat16(b - __bfloat162float(hb));
    __nv_bfloat162 hv(ha, hb), lv(la, lb);
    h = *(uint32_t*)&hv; l = *(uint32_t*)&lv;
}
__device__ __forceinline__ void cp16(__nv_bfloat16* dst, const __nv_bfloat16* src) {
    asm volatile("cp.async.cg.shared.global [%0], [%1], 16;"
        :: "r"(sptr(dst)), "l"(src));
}
#define CP_COMMIT() asm volatile("cp.async.commit_group;")
#define CP_WAIT1()  asm volatile("cp.async.wait_group 1;" ::: "memory")

// ---------------------------------------------------------------------------
// fp32 -> bf16 hi/lo split (inputs only)
// ---------------------------------------------------------------------------
__global__ __launch_bounds__(256) void split_kernel(
    const float4* __restrict__ in, uint2* __restrict__ hi,
    uint2* __restrict__ lo, int n4)
{
    for (int i = blockIdx.x * blockDim.x + threadIdx.x; i < n4;
         i += gridDim.x * blockDim.x) {
        float4 v = in[i];
        float f[4] = {v.x, v.y, v.z, v.w};
        __nv_bfloat16 h[4], l[4];
#pragma unroll
        for (int j = 0; j < 4; j++) {
            h[j] = __float2bfloat16(f[j]);
            l[j] = __float2bfloat16(f[j] - __bfloat162float(h[j]));
        }
        hi[i] = *(uint2*)h;
        lo[i] = *(uint2*)l;
    }
}

// ---------------------------------------------------------------------------
// Pipelined bf16x3 GEMM core. 128x128x32 tile, 2-stage cp.async.
// 256 thr, 8 warps (2x4), warp tile 64x32.
// Dynamic smem layout: sA[st][hl][128][APAD], sB[st][hl][32][BPAD]
// ---------------------------------------------------------------------------
#define TBM 128
#define TBN 128
#define TBK 32
#define APAD 48
#define BPAD 136
#define SA_ST (2 * TBM * APAD)                 // elems per A stage (hi+lo)
#define SB_ST (2 * TBK * BPAD)
#define GEMM_SMEM ((2 * SA_ST + 2 * SB_ST) * 2)  // bytes = 83968

struct GemmPtrs {
    const __nv_bfloat16 *Ah, *Al, *Bh, *Bl;
    float* C;
    __nv_bfloat16 *Ch, *Cl;
    int N, bn, bm;
};

template<bool BF16OUT>
__device__ __forceinline__ void gemm_body(const GemmPtrs& g, int K)
{
    extern __shared__ __nv_bfloat16 dyn[];
    __nv_bfloat16* sA = dyn;                  // [st][hl][TBM][APAD]
    __nv_bfloat16* sB = dyn + 2 * SA_ST;      // [st][hl][TBK][BPAD]

    const int tid  = threadIdx.x;
    const int lane = tid & 31;
    const int warp = tid >> 5;
    const int wm = warp >> 2, wn = warp & 3;
    const int N = g.N, bm = g.bm, bn = g.bn;

    const int arow = tid >> 2;          // 0..63, two passes
    const int acol = (tid & 3) * 8;     // 16B chunks over TBK=32
    const int brow = tid >> 4;          // 0..15, two passes
    const int bn8  = (tid & 15) * 8;

    const int nsteps = K / TBK;

    auto load_stage = [&](int st, int k0) {
        __nv_bfloat16* aH = sA + st * SA_ST;
        __nv_bfloat16* aL = aH + TBM * APAD;
        __nv_bfloat16* bH = sB + st * SB_ST;
        __nv_bfloat16* bL = bH + TBK * BPAD;
#pragma unroll
        for (int p = 0; p < 2; p++) {
            int r = arow + p * 64;
            size_t gi = (size_t)(bm + r) * K + k0 + acol;
            cp16(aH + r * APAD + acol, g.Ah + gi);
            cp16(aL + r * APAD + acol, g.Al + gi);
        }
#pragma unroll
        for (int p = 0; p < 2; p++) {
            int r = brow + p * 16;
            size_t gi = (size_t)(k0 + r) * N + bn + bn8;
            cp16(bH + r * BPAD + bn8, g.Bh + gi);
            cp16(bL + r * BPAD + bn8, g.Bl + gi);
        }
    };

    float acc[4][4][4];
#pragma unroll
    for (int mi = 0; mi < 4; mi++)
#pragma unroll
        for (int nj = 0; nj < 4; nj++)
#pragma unroll
            for (int v = 0; v < 4; v++) acc[mi][nj][v] = 0.f;

    load_stage(0, 0);
    CP_COMMIT();

    for (int ks = 0; ks < nsteps; ks++) {
        int cur = ks & 1;
        if (ks + 1 < nsteps) load_stage(cur ^ 1, (ks + 1) * TBK);
        CP_COMMIT();
        CP_WAIT1();
        __syncthreads();

        const __nv_bfloat16* cAh = sA + cur * SA_ST;
        const __nv_bfloat16* cAl = cAh + TBM * APAD;
        const __nv_bfloat16* cBh = sB + cur * SB_ST;
        const __nv_bfloat16* cBl = cBh + TBK * BPAD;

#pragma unroll
        for (int kk = 0; kk < TBK; kk += 16) {
            uint32_t ah[4][4], al[4][4], bh[4][2], bl[4][2];
#pragma unroll
            for (int mi = 0; mi < 4; mi++) {
                int row = wm * 64 + mi * 16 + (lane & 15);
                int col = kk + (lane >> 4) * 8;
                ldsm_x4(ah[mi], sptr(cAh + row * APAD + col));
                ldsm_x4(al[mi], sptr(cAl + row * APAD + col));
            }
#pragma unroll
            for (int nj = 0; nj < 4; nj++) {
                int r = kk + (lane & 15);
                int c = wn * 32 + nj * 8;
                ldsm_x2t(bh[nj], sptr(cBh + r * BPAD + c));
                ldsm_x2t(bl[nj], sptr(cBl + r * BPAD + c));
            }
#pragma unroll
            for (int mi = 0; mi < 4; mi++)
#pragma unroll
                for (int nj = 0; nj < 4; nj++) {
                    mma16816(acc[mi][nj], ah[mi], bh[nj]);
                    mma16816(acc[mi][nj], ah[mi], bl[nj]);
                    mma16816(acc[mi][nj], al[mi], bh[nj]);
                }
        }
        __syncthreads();
    }

#pragma unroll
    for (int mi = 0; mi < 4; mi++)
#pragma unroll
        for (int nj = 0; nj < 4; nj++) {
            int row = bm + wm * 64 + mi * 16 + (lane >> 2);
            int col = bn + wn * 32 + nj * 8 + (lane & 3) * 2;
            if (BF16OUT) {
                uint32_t hv, lv;
                split2(acc[mi][nj][0], acc[mi][nj][1], hv, lv);
                *(uint32_t*)&g.Ch[(size_t)row * N + col] = hv;
                *(uint32_t*)&g.Cl[(size_t)row * N + col] = lv;
                split2(acc[mi][nj][2], acc[mi][nj][3], hv, lv);
                *(uint32_t*)&g.Ch[(size_t)(row + 8) * N + col] = hv;
                *(uint32_t*)&g.Cl[(size_t)(row + 8) * N + col] = lv;
            } else {
                *(float2*)&g.C[(size_t)row * N + col] =
                    make_float2(acc[mi][nj][0], acc[mi][nj][1]);
                *(float2*)&g.C[(size_t)(row + 8) * N + col] =
                    make_float2(acc[mi][nj][2], acc[mi][nj][3]);
            }
        }
}

// Fused Q/K/V projection: blockIdx.x in [0,24): 0-15 Q, 16-19 K, 20-23 V
__global__ __launch_bounds__(256) void qkv_gemm(
    const __nv_bfloat16* __restrict__ xh, const __nv_bfloat16* __restrict__ xl,
    const __nv_bfloat16* __restrict__ Wqh, const __nv_bfloat16* __restrict__ Wql,
    const __nv_bfloat16* __restrict__ Wkh, const __nv_bfloat16* __restrict__ Wkl,
    const __nv_bfloat16* __restrict__ Wvh, const __nv_bfloat16* __restrict__ Wvl,
    __nv_bfloat16* __restrict__ Qh, __nv_bfloat16* __restrict__ Ql,
    __nv_bfloat16* __restrict__ Kh, __nv_bfloat16* __restrict__ Kl,
    __nv_bfloat16* __restrict__ Vh, __nv_bfloat16* __restrict__ Vl)
{
    GemmPtrs g;
    g.Ah = xh; g.Al = xl; g.C = nullptr;
    g.bm = blockIdx.y * TBM;
    int nb = blockIdx.x;
    if (nb < 16)      { g.Bh = Wqh; g.Bl = Wql; g.Ch = Qh; g.Cl = Ql; g.N = NQ;  g.bn = nb * TBN; }
    else if (nb < 20) { g.Bh = Wkh; g.Bl = Wkl; g.Ch = Kh; g.Cl = Kl; g.N = NKV; g.bn = (nb - 16) * TBN; }
    else              { g.Bh = Wvh; g.Bl = Wvl; g.Ch = Vh; g.Cl = Vl; g.N = NKV; g.bn = (nb - 20) * TBN; }
    gemm_body<true>(g, DD);
}

// Output projection: fp32 out
__global__ __launch_bounds__(256) void out_gemm(
    const __nv_bfloat16* __restrict__ Ah, const __nv_bfloat16* __restrict__ Al,
    const __nv_bfloat16* __restrict__ Bh, const __nv_bfloat16* __restrict__ Bl,
    float* __restrict__ C)
{
    GemmPtrs g;
    g.Ah = Ah; g.Al = Al; g.Bh = Bh; g.Bl = Bl;
    g.C = C; g.Ch = nullptr; g.Cl = nullptr;
    g.N = DD; g.bn = blockIdx.x * TBN; g.bm = blockIdx.y * TBM;
    gemm_body<false>(g, NQ);
}

// ---------------------------------------------------------------------------
// Flash attention, bf16x3 mma, 2-stage cp.async K/V pipeline.
// Block: 128 q-rows x one (b,h). 8 warps x 16-row bands. 64-kv tiles.
// ---------------------------------------------------------------------------
#define FP 72
#define KVSTG (4 * 64 * FP)                       // elems per KV stage
#define FLASH_SMEM ((256 * FP + 2 * KVSTG) * 2)   // 110592 bytes

__global__ __launch_bounds__(256) void flash_mma(
    const __nv_bfloat16* __restrict__ Qh, const __nv_bfloat16* __restrict__ Ql,
    const __nv_bfloat16* __restrict__ Kh, const __nv_bfloat16* __restrict__ Kl,
    const __nv_bfloat16* __restrict__ Vh, const __nv_bfloat16* __restrict__ Vl,
    __nv_bfloat16* __restrict__ Ch, __nv_bfloat16* __restrict__ Cl)
{
    extern __shared__ __nv_bfloat16 smf[];
    __nv_bfloat16* sQh = smf;
    __nv_bfloat16* sQl = smf + 128 * FP;
    __nv_bfloat16* kvb = smf + 256 * FP;   // [st][4][64][FP] : Kh,Kl,Vh,Vl

    const int tid = threadIdx.x, lane = tid & 31, warp = tid >> 5;
    const int qb = blockIdx.x, h = blockIdx.y, b = blockIdx.z;
    const int kvh = h >> 2;
    const int qbase = qb * 128;

    const int kvrow = tid >> 2;
    const int kvc   = tid & 3;

    auto load_kv = [&](int st, int kt) {
        size_t g = (size_t)(b * SS + kt * 64 + kvrow) * NKV + kvh * DH;
        __nv_bfloat16* dK = kvb + st * KVSTG + kvrow * FP;
#pragma unroll
        for (int p = 0; p < 2; p++) {
            int c = (kvc + p * 4) * 8;
            cp16(dK + c,               Kh + g + c);
            cp16(dK + 64 * FP + c,     Kl + g + c);
            cp16(dK + 128 * FP + c,    Vh + g + c);
            cp16(dK + 192 * FP + c,    Vl + g + c);
        }
    };

    // load Q tile (hi/lo)
    {
        int row = tid >> 1;
        int cb  = (tid & 1) * 4;
        size_t g = (size_t)(b * SS + qbase + row) * NQ + h * DH;
#pragma unroll
        for (int c = 0; c < 4; c++) {
            ((uint4*)(sQh + row * FP))[cb + c] = ((const uint4*)(Qh + g))[cb + c];
            ((uint4*)(sQl + row * FP))[cb + c] = ((const uint4*)(Ql + g))[cb + c];
        }
    }

    float o[8][4];
#pragma unroll
    for (int t = 0; t < 8; t++)
#pragma unroll
        for (int v = 0; v < 4; v++) o[t][v] = 0.f;
    float mrow[2] = {-1e30f, -1e30f}, lrow[2] = {0.f, 0.f};

    load_kv(0, 0);
    CP_COMMIT();

    for (int kt = 0; kt < SS / 64; kt++) {
        int cur = kt & 1;
        if (kt + 1 < SS / 64) load_kv(cur ^ 1, kt + 1);
        CP_COMMIT();
        CP_WAIT1();
        __syncthreads();

        const __nv_bfloat16* sKh = kvb + cur * KVSTG;
        const __nv_bfloat16* sKl = sKh + 64 * FP;
        const __nv_bfloat16* sVh = sKh + 128 * FP;
        const __nv_bfloat16* sVl = sKh + 192 * FP;

        // ---- S = Q K^T ----
        float s[8][4];
#pragma unroll
        for (int t = 0; t < 8; t++)
#pragma unroll
            for (int v = 0; v < 4; v++) s[t][v] = 0.f;

#pragma unroll
        for (int ks = 0; ks < 4; ks++) {
            uint32_t qhf[4], qlf[4];
            uint32_t qa = (warp * 16 + (lane & 15)) * FP + ks * 16 + (lane >> 4) * 8;
            ldsm_x4(qhf, sptr(sQh + qa));
            ldsm_x4(qlf, sptr(sQl + qa));
#pragma unroll
            for (int np = 0; np < 4; np++) {
                uint32_t kh4[4], kl4[4];
                uint32_t ka = (np * 16 + (lane & 7) + ((lane >> 4) << 3)) * FP
                            + ks * 16 + ((lane >> 3) & 1) * 8;
                ldsm_x4(kh4, sptr(sKh + ka));
                ldsm_x4(kl4, sptr(sKl + ka));
                mma16816(s[2*np],   qhf, &kh4[0]);
                mma16816(s[2*np],   qlf, &kh4[0]);
                mma16816(s[2*np],   qhf, &kl4[0]);
                mma16816(s[2*np+1], qhf, &kh4[2]);
                mma16816(s[2*np+1], qlf, &kh4[2]);
                mma16816(s[2*np+1], qhf, &kl4[2]);
            }
        }

        // ---- online softmax ----
        float mx0 = -1e30f, mx1 = -1e30f;
#pragma unroll
        for (int t = 0; t < 8; t++) {
#pragma unroll
            for (int v = 0; v < 4; v++) s[t][v] *= 0.125f;
            mx0 = fmaxf(mx0, fmaxf(s[t][0], s[t][1]));
            mx1 = fmaxf(mx1, fmaxf(s[t][2], s[t][3]));
        }
#pragma unroll
        for (int off = 1; off <= 2; off <<= 1) {
            mx0 = fmaxf(mx0, __shfl_xor_sync(0xffffffffu, mx0, off));
            mx1 = fmaxf(mx1, __shfl_xor_sync(0xffffffffu, mx1, off));
        }
        float mn0 = fmaxf(mrow[0], mx0), mn1 = fmaxf(mrow[1], mx1);
        float fac0 = __expf(mrow[0] - mn0), fac1 = __expf(mrow[1] - mn1);
        mrow[0] = mn0; mrow[1] = mn1;
        float ls0 = 0.f, ls1 = 0.f;
#pragma unroll
        for (int t = 0; t < 8; t++) {
            s[t][0] = __expf(s[t][0] - mn0); ls0 += s[t][0];
            s[t][1] = __expf(s[t][1] - mn0); ls0 += s[t][1];
            s[t][2] = __expf(s[t][2] - mn1); ls1 += s[t][2];
            s[t][3] = __expf(s[t][3] - mn1); ls1 += s[t][3];
        }
#pragma unroll
        for (int off = 1; off <= 2; off <<= 1) {
            ls0 += __shfl_xor_sync(0xffffffffu, ls0, off);
            ls1 += __shfl_xor_sync(0xffffffffu, ls1, off);
        }
        lrow[0] = lrow[0] * fac0 + ls0;
        lrow[1] = lrow[1] * fac1 + ls1;
#pragma unroll
        for (int t = 0; t < 8; t++) {
            o[t][0] *= fac0; o[t][1] *= fac0;
            o[t][2] *= fac1; o[t][3] *= fac1;
        }

        // ---- O += P V ----
#pragma unroll
        for (int j = 0; j < 4; j++) {
            uint32_t pah[4], pal[4];
            split2(s[2*j][0],   s[2*j][1],   pah[0], pal[0]);
            split2(s[2*j][2],   s[2*j][3],   pah[1], pal[1]);
            split2(s[2*j+1][0], s[2*j+1][1], pah[2], pal[2]);
            split2(s[2*j+1][2], s[2*j+1][3], pah[3], pal[3]);
#pragma unroll
            for (int np = 0; np < 4; np++) {
                uint32_t vh4[4], vl4[4];
                uint32_t va = (j * 16 + (lane & 15)) * FP + np * 16 + (lane >> 4) * 8;
                ldsm_x4t(vh4, sptr(sVh + va));
                ldsm_x4t(vl4, sptr(sVl + va));
                mma16816(o[2*np],   pah, &vh4[0]);
                mma16816(o[2*np],   pal, &vh4[0]);
                mma16816(o[2*np],   pah, &vl4[0]);
                mma16816(o[2*np+1], pah, &vh4[2]);
                mma16816(o[2*np+1], pal, &vh4[2]);
                mma16816(o[2*np+1], pah, &vl4[2]);
            }
        }
        __syncthreads();
    }

    // ---- epilogue ----
    float inv0 = 1.f / lrow[0], inv1 = 1.f / lrow[1];
    int r0 = qbase + warp * 16 + (lane >> 2);
    size_t base0 = (size_t)(b * SS + r0) * NQ + h * DH + (lane & 3) * 2;
    size_t base1 = base0 + (size_t)8 * NQ;
#pragma unroll
    for (int t = 0; t < 8; t++) {
        uint32_t hv, lv;
        split2(o[t][0] * inv0, o[t][1] * inv0, hv, lv);
        *(uint32_t*)&Ch[base0 + t * 8] = hv;
        *(uint32_t*)&Cl[base0 + t * 8] = lv;
        split2(o[t][2] * inv1, o[t][3] * inv1, hv, lv);
        *(uint32_t*)&Ch[base1 + t * 8] = hv;
        *(uint32_t*)&Cl[base1 + t * 8] = lv;
    }
}

// ---------------------------------------------------------------------------
// Launch
// ---------------------------------------------------------------------------
static void split(const float* src, __nv_bfloat16* h, __nv_bfloat16* l, size_t n)
{
    int n4 = (int)(n / 4);
    int blocks = (n4 + 255) / 256;
    if (blocks > 4096) blocks = 4096;
    split_kernel<<<blocks, 256>>>((const float4*)src, (uint2*)h, (uint2*)l, n4);
}

extern "C" void kernel_launch(void* const* d_in, const int* in_sizes, int n_in,
                              void* d_out, int out_size)
{
    const float* x  = (const float*)d_in[0];
    const float* Wq = (const float*)d_in[1];
    const float* Wk = (const float*)d_in[2];
    const float* Wv = (const float*)d_in[3];
    const float* Wo = (const float*)d_in[4];
    float* out = (float*)d_out;

    __nv_bfloat16 *xh, *xl, *Wqh, *Wql, *Wkh, *Wkl, *Wvh, *Wvl, *Woh, *Wol;
    __nv_bfloat16 *Qh, *Ql, *Kh, *Kl, *Vh, *Vl, *Ch, *Cl;
    cudaGetSymbolAddress((void**)&xh,  g_xh);  cudaGetSymbolAddress((void**)&xl,  g_xl);
    cudaGetSymbolAddress((void**)&Wqh, g_Wqh); cudaGetSymbolAddress((void**)&Wql, g_Wql);
    cudaGetSymbolAddress((void**)&Wkh, g_Wkh); cudaGetSymbolAddress((void**)&Wkl, g_Wkl);
    cudaGetSymbolAddress((void**)&Wvh, g_Wvh); cudaGetSymbolAddress((void**)&Wvl, g_Wvl);
    cudaGetSymbolAddress((void**)&Woh, g_Woh); cudaGetSymbolAddress((void**)&Wol, g_Wol);
    cudaGetSymbolAddress((void**)&Qh,  g_Qh);  cudaGetSymbolAddress((void**)&Ql,  g_Ql);
    cudaGetSymbolAddress((void**)&Kh,  g_Kh);  cudaGetSymbolAddress((void**)&Kl,  g_Kl);
    cudaGetSymbolAddress((void**)&Vh,  g_Vh);  cudaGetSymbolAddress((void**)&Vl,  g_Vl);
    cudaGetSymbolAddress((void**)&Ch,  g_Ch);  cudaGetSymbolAddress((void**)&Cl,  g_Cl);

    cudaFuncSetAttribute(qkv_gemm,
                         cudaFuncAttributeMaxDynamicSharedMemorySize, GEMM_SMEM);
    cudaFuncSetAttribute(out_gemm,
                         cudaFuncAttributeMaxDynamicSharedMemorySize, GEMM_SMEM);
    cudaFuncSetAttribute(flash_mma,
                         cudaFuncAttributeMaxDynamicSharedMemorySize, FLASH_SMEM);

    // split inputs
    split(x,  xh,  xl,  (size_t)MROWS * DD);
    split(Wq, Wqh, Wql, (size_t)DD * NQ);
    split(Wk, Wkh, Wkl, (size_t)DD * NKV);
    split(Wv, Wvh, Wvl, (size_t)DD * NKV);
    split(Wo, Woh, Wol, (size_t)NQ * DD);

    // fused Q/K/V projection (tensor cores, pipelined)
    qkv_gemm<<<dim3(24, MROWS / TBM), 256, GEMM_SMEM>>>(
        xh, xl, Wqh, Wql, Wkh, Wkl, Wvh, Wvl, Qh, Ql, Kh, Kl, Vh, Vl);

    // attention (tensor cores, pipelined KV)
    flash_mma<<<dim3(SS / 128, HQ, BB), 256, FLASH_SMEM>>>(
        Qh, Ql, Kh, Kl, Vh, Vl, Ch, Cl);

    // output projection
    out_gemm<<<dim3(DD / TBN, MROWS / TBM), 256, GEMM_SMEM>>>(
        Ch, Cl, Woh, Wol, out);
}

// round 7
// speedup vs baseline: 3.1547x; 1.0971x over previous
#include <cuda_runtime.h>
#include <cuda_bf16.h>
#include <math.h>
#include <stdint.h>

// Problem constants
#define BB    2
#define SS    2048
#define DD    2048
#define HQ    32
#define HKV   8
#define DH    64
#define MROWS (BB*SS)          // 4096
#define NQ    (HQ*DH)          // 2048
#define NKV   (HKV*DH)         // 512

// ---------------------------------------------------------------------------
// Scratch (allocation-free rule: device globals). All intermediates bf16 hi/lo.
// ---------------------------------------------------------------------------
__device__ __nv_bfloat16 g_xh[(size_t)MROWS * DD],  g_xl[(size_t)MROWS * DD];
__device__ __nv_bfloat16 g_Wqh[(size_t)DD * NQ],    g_Wql[(size_t)DD * NQ];
__device__ __nv_bfloat16 g_Wkh[(size_t)DD * NKV],   g_Wkl[(size_t)DD * NKV];
__device__ __nv_bfloat16 g_Wvh[(size_t)DD * NKV],   g_Wvl[(size_t)DD * NKV];
__device__ __nv_bfloat16 g_Woh[(size_t)NQ * DD],    g_Wol[(size_t)NQ * DD];
__device__ __nv_bfloat16 g_Qh[(size_t)MROWS * NQ],  g_Ql[(size_t)MROWS * NQ];
__device__ __nv_bfloat16 g_Kh[(size_t)MROWS * NKV], g_Kl[(size_t)MROWS * NKV];
__device__ __nv_bfloat16 g_Vh[(size_t)MROWS * NKV], g_Vl[(size_t)MROWS * NKV];
__device__ __nv_bfloat16 g_Ch[(size_t)MROWS * NQ],  g_Cl[(size_t)MROWS * NQ];

// ---------------------------------------------------------------------------
// helpers
// ---------------------------------------------------------------------------
__device__ __forceinline__ uint32_t sptr(const void* p) {
    return (uint32_t)__cvta_generic_to_shared(p);
}
__device__ __forceinline__ void ldsm_x4(uint32_t* r, uint32_t a) {
    asm volatile("ldmatrix.sync.aligned.m8n8.x4.shared.b16 {%0,%1,%2,%3}, [%4];"
        : "=r"(r[0]), "=r"(r[1]), "=r"(r[2]), "=r"(r[3]) : "r"(a));
}
__device__ __forceinline__ void ldsm_x4t(uint32_t* r, uint32_t a) {
    asm volatile("ldmatrix.sync.aligned.m8n8.x4.trans.shared.b16 {%0,%1,%2,%3}, [%4];"
        : "=r"(r[0]), "=r"(r[1]), "=r"(r[2]), "=r"(r[3]) : "r"(a));
}
__device__ __forceinline__ void mma16816(float* c, const uint32_t* a, const uint32_t* b) {
    asm volatile(
        "mma.sync.aligned.m16n8k16.row.col.f32.bf16.bf16.f32 "
        "{%0,%1,%2,%3}, {%4,%5,%6,%7}, {%8,%9}, {%0,%1,%2,%3};"
        : "+f"(c[0]), "+f"(c[1]), "+f"(c[2]), "+f"(c[3])
        : "r"(a[0]), "r"(a[1]), "r"(a[2]), "r"(a[3]), "r"(b[0]), "r"(b[1]));
}
__device__ __forceinline__ void split2(float a, float b, uint32_t& h, uint32_t& l) {
    __nv_bfloat16 ha = __float2bfloat16(a), hb = __float2bfloat16(b);
    __nv_bfloat16 la = __float2bfloat16(a - __bfloat162float(ha));
    __nv_bfloat16 lb = __float2bfloat16(b - __bfloat162float(hb));
    __nv_bfloat162 hv(ha, hb), lv(la, lb);
    h = *(uint32_t*)&hv; l = *(uint32_t*)&lv;
}
__device__ __forceinline__ void cp16(__nv_bfloat16* dst, const __nv_bfloat16* src) {
    asm volatile("cp.async.cg.shared.global [%0], [%1], 16;"
        :: "r"(sptr(dst)), "l"(src));
}
__device__ __forceinline__ void cp16s(uint32_t daddr, const void* src) {
    asm volatile("cp.async.cg.shared.global [%0], [%1], 16;"
        :: "r"(daddr), "l"(src));
}
#define CP_COMMIT() asm volatile("cp.async.commit_group;")
#define CP_WAIT1()  asm volatile("cp.async.wait_group 1;" ::: "memory")

// ---------------------------------------------------------------------------
// fp32 -> bf16 hi/lo split (inputs only)
// ---------------------------------------------------------------------------
__global__ __launch_bounds__(256) void split_kernel(
    const float4* __restrict__ in, uint2* __restrict__ hi,
    uint2* __restrict__ lo, int n4)
{
    for (int i = blockIdx.x * blockDim.x + threadIdx.x; i < n4;
         i += gridDim.x * blockDim.x) {
        float4 v = in[i];
        float f[4] = {v.x, v.y, v.z, v.w};
        __nv_bfloat16 h[4], l[4];
#pragma unroll
        for (int j = 0; j < 4; j++) {
            h[j] = __float2bfloat16(f[j]);
            l[j] = __float2bfloat16(f[j] - __bfloat162float(h[j]));
        }
        hi[i] = *(uint2*)h;
        lo[i] = *(uint2*)l;
    }
}

// ---------------------------------------------------------------------------
// Pipelined bf16x3 GEMM. 128x128x32 tile, 3-stage cp.async, 1 sync/iter.
// 256 thr, 8 warps (2x4), warp tile 64x32.
// A smem: 64B rows, SW64 XOR swizzle (conflict-free ldsm + cp.async).
// B smem: [32][136] rows (272B, conflict-free), ldsm_x4t (n16 per load).
// ---------------------------------------------------------------------------
#define TBM 128
#define TBN 128
#define TBK 32
#define BPAD 136
#define ABYT (TBM * TBK * 2)            // 8192 B per A hi/lo buffer
#define BBYT (TBK * BPAD * 2)           // 8704 B per B hi/lo buffer
#define STG  (2 * ABYT + 2 * BBYT)      // 33792 B per stage
#define GEMM_SMEM (3 * STG)             // 101376 B

// swizzled byte offset for A: row r (0..127), 16B chunk c (0..3)
__device__ __forceinline__ uint32_t swzA(uint32_t r, uint32_t c) {
    return r * 64 + ((c ^ ((r >> 1) & 3)) << 4);
}

struct GemmPtrs {
    const __nv_bfloat16 *Ah, *Al, *Bh, *Bl;
    float* C;
    __nv_bfloat16 *Ch, *Cl;
    int N, bn, bm;
};

template<bool BF16OUT>
__device__ __forceinline__ void gemm_body(const GemmPtrs& g, int K)
{
    extern __shared__ __nv_bfloat16 dyn[];
    const uint32_t sb = sptr(dyn);

    const int tid  = threadIdx.x;
    const int lane = tid & 31;
    const int warp = tid >> 5;
    const int wm = warp >> 2, wn = warp & 3;
    const int N = g.N, bm = g.bm, bn = g.bn;

    const int arow = tid >> 2;          // 0..63, two passes (+64)
    const int ac   = tid & 3;           // A chunk 0..3
    const int brow = tid >> 4;          // 0..15, two passes (+16)
    const int bn8  = (tid & 15) * 8;

    const int nsteps = K / TBK;

    auto load_stage = [&](int st, int k0) {
        const uint32_t S  = sb + st * STG;
        const uint32_t aH = S, aL = S + ABYT;
        const uint32_t bH = S + 2 * ABYT, bL = bH + BBYT;
#pragma unroll
        for (int p = 0; p < 2; p++) {
            int r = arow + p * 64;
            size_t gi = (size_t)(bm + r) * K + k0 + ac * 8;
            uint32_t so = swzA(r, ac);
            cp16s(aH + so, g.Ah + gi);
            cp16s(aL + so, g.Al + gi);
        }
#pragma unroll
        for (int p = 0; p < 2; p++) {
            int r = brow + p * 16;
            size_t gi = (size_t)(k0 + r) * N + bn + bn8;
            uint32_t so = r * (BPAD * 2) + bn8 * 2;
            cp16s(bH + so, g.Bh + gi);
            cp16s(bL + so, g.Bl + gi);
        }
    };

    float acc[4][4][4];
#pragma unroll
    for (int mi = 0; mi < 4; mi++)
#pragma unroll
        for (int nj = 0; nj < 4; nj++)
#pragma unroll
            for (int v = 0; v < 4; v++) acc[mi][nj][v] = 0.f;

    load_stage(0, 0);
    CP_COMMIT();
    load_stage(1, TBK);
    CP_COMMIT();

    for (int ks = 0; ks < nsteps; ks++) {
        const int cur = ks % 3;
        CP_WAIT1();          // stage ks complete (ks+1 may still be in flight)
        __syncthreads();     // everyone done computing stage ks-1 -> its buffer free
        if (ks + 2 < nsteps) load_stage((ks + 2) % 3, (ks + 2) * TBK);
        CP_COMMIT();

        const uint32_t S  = sb + cur * STG;
        const uint32_t aH = S, aL = S + ABYT;
        const uint32_t bH = S + 2 * ABYT, bL = bH + BBYT;

#pragma unroll
        for (int kk = 0; kk < TBK; kk += 16) {
            uint32_t ah[4][4], al[4][4];
#pragma unroll
            for (int mi = 0; mi < 4; mi++) {
                uint32_t row = wm * 64 + mi * 16 + (lane & 15);
                uint32_t c   = (kk >> 3) + (lane >> 4);
                uint32_t so  = swzA(row, c);
                ldsm_x4(ah[mi], aH + so);
                ldsm_x4(al[mi], aL + so);
            }
#pragma unroll
            for (int nj2 = 0; nj2 < 2; nj2++) {
                uint32_t bh4[4], bl4[4];
                uint32_t row = kk + (lane & 15);
                uint32_t col = wn * 32 + nj2 * 16 + (lane >> 4) * 8;
                uint32_t so  = row * (BPAD * 2) + col * 2;
                ldsm_x4t(bh4, bH + so);
                ldsm_x4t(bl4, bL + so);
#pragma unroll
                for (int mi = 0; mi < 4; mi++) {
                    mma16816(acc[mi][2*nj2],   ah[mi], &bh4[0]);
                    mma16816(acc[mi][2*nj2],   al[mi], &bh4[0]);
                    mma16816(acc[mi][2*nj2],   ah[mi], &bl4[0]);
                    mma16816(acc[mi][2*nj2+1], ah[mi], &bh4[2]);
                    mma16816(acc[mi][2*nj2+1], al[mi], &bh4[2]);
                    mma16816(acc[mi][2*nj2+1], ah[mi], &bl4[2]);
                }
            }
        }
    }

#pragma unroll
    for (int mi = 0; mi < 4; mi++)
#pragma unroll
        for (int nj = 0; nj < 4; nj++) {
            int row = bm + wm * 64 + mi * 16 + (lane >> 2);
            int col = bn + wn * 32 + nj * 8 + (lane & 3) * 2;
            if (BF16OUT) {
                uint32_t hv, lv;
                split2(acc[mi][nj][0], acc[mi][nj][1], hv, lv);
                *(uint32_t*)&g.Ch[(size_t)row * N + col] = hv;
                *(uint32_t*)&g.Cl[(size_t)row * N + col] = lv;
                split2(acc[mi][nj][2], acc[mi][nj][3], hv, lv);
                *(uint32_t*)&g.Ch[(size_t)(row + 8) * N + col] = hv;
                *(uint32_t*)&g.Cl[(size_t)(row + 8) * N + col] = lv;
            } else {
                *(float2*)&g.C[(size_t)row * N + col] =
                    make_float2(acc[mi][nj][0], acc[mi][nj][1]);
                *(float2*)&g.C[(size_t)(row + 8) * N + col] =
                    make_float2(acc[mi][nj][2], acc[mi][nj][3]);
            }
        }
}

// Fused Q/K/V projection: blockIdx.x in [0,24): 0-15 Q, 16-19 K, 20-23 V
__global__ __launch_bounds__(256, 2) void qkv_gemm(
    const __nv_bfloat16* __restrict__ xh, const __nv_bfloat16* __restrict__ xl,
    const __nv_bfloat16* __restrict__ Wqh, const __nv_bfloat16* __restrict__ Wql,
    const __nv_bfloat16* __restrict__ Wkh, const __nv_bfloat16* __restrict__ Wkl,
    const __nv_bfloat16* __restrict__ Wvh, const __nv_bfloat16* __restrict__ Wvl,
    __nv_bfloat16* __restrict__ Qh, __nv_bfloat16* __restrict__ Ql,
    __nv_bfloat16* __restrict__ Kh, __nv_bfloat16* __restrict__ Kl,
    __nv_bfloat16* __restrict__ Vh, __nv_bfloat16* __restrict__ Vl)
{
    GemmPtrs g;
    g.Ah = xh; g.Al = xl; g.C = nullptr;
    g.bm = blockIdx.y * TBM;
    int nb = blockIdx.x;
    if (nb < 16)      { g.Bh = Wqh; g.Bl = Wql; g.Ch = Qh; g.Cl = Ql; g.N = NQ;  g.bn = nb * TBN; }
    else if (nb < 20) { g.Bh = Wkh; g.Bl = Wkl; g.Ch = Kh; g.Cl = Kl; g.N = NKV; g.bn = (nb - 16) * TBN; }
    else              { g.Bh = Wvh; g.Bl = Wvl; g.Ch = Vh; g.Cl = Vl; g.N = NKV; g.bn = (nb - 20) * TBN; }
    gemm_body<true>(g, DD);
}

// Output projection: fp32 out
__global__ __launch_bounds__(256, 2) void out_gemm(
    const __nv_bfloat16* __restrict__ Ah, const __nv_bfloat16* __restrict__ Al,
    const __nv_bfloat16* __restrict__ Bh, const __nv_bfloat16* __restrict__ Bl,
    float* __restrict__ C)
{
    GemmPtrs g;
    g.Ah = Ah; g.Al = Al; g.Bh = Bh; g.Bl = Bl;
    g.C = C; g.Ch = nullptr; g.Cl = nullptr;
    g.N = DD; g.bn = blockIdx.x * TBN; g.bm = blockIdx.y * TBM;
    gemm_body<false>(g, NQ);
}

// ---------------------------------------------------------------------------
// Flash attention, bf16x3 mma, 2-stage cp.async K/V pipeline (unchanged R4).
// ---------------------------------------------------------------------------
#define FP 72
#define KVSTG (4 * 64 * FP)
#define FLASH_SMEM ((256 * FP + 2 * KVSTG) * 2)

__global__ __launch_bounds__(256) void flash_mma(
    const __nv_bfloat16* __restrict__ Qh, const __nv_bfloat16* __restrict__ Ql,
    const __nv_bfloat16* __restrict__ Kh, const __nv_bfloat16* __restrict__ Kl,
    const __nv_bfloat16* __restrict__ Vh, const __nv_bfloat16* __restrict__ Vl,
    __nv_bfloat16* __restrict__ Ch, __nv_bfloat16* __restrict__ Cl)
{
    extern __shared__ __nv_bfloat16 smf[];
    __nv_bfloat16* sQh = smf;
    __nv_bfloat16* sQl = smf + 128 * FP;
    __nv_bfloat16* kvb = smf + 256 * FP;

    const int tid = threadIdx.x, lane = tid & 31, warp = tid >> 5;
    const int qb = blockIdx.x, h = blockIdx.y, b = blockIdx.z;
    const int kvh = h >> 2;
    const int qbase = qb * 128;

    const int kvrow = tid >> 2;
    const int kvc   = tid & 3;

    auto load_kv = [&](int st, int kt) {
        size_t g = (size_t)(b * SS + kt * 64 + kvrow) * NKV + kvh * DH;
        __nv_bfloat16* dK = kvb + st * KVSTG + kvrow * FP;
#pragma unroll
        for (int p = 0; p < 2; p++) {
            int c = (kvc + p * 4) * 8;
            cp16(dK + c,            Kh + g + c);
            cp16(dK + 64 * FP + c,  Kl + g + c);
            cp16(dK + 128 * FP + c, Vh + g + c);
            cp16(dK + 192 * FP + c, Vl + g + c);
        }
    };

    {
        int row = tid >> 1;
        int cb  = (tid & 1) * 4;
        size_t g = (size_t)(b * SS + qbase + row) * NQ + h * DH;
#pragma unroll
        for (int c = 0; c < 4; c++) {
            ((uint4*)(sQh + row * FP))[cb + c] = ((const uint4*)(Qh + g))[cb + c];
            ((uint4*)(sQl + row * FP))[cb + c] = ((const uint4*)(Ql + g))[cb + c];
        }
    }

    float o[8][4];
#pragma unroll
    for (int t = 0; t < 8; t++)
#pragma unroll
        for (int v = 0; v < 4; v++) o[t][v] = 0.f;
    float mrow[2] = {-1e30f, -1e30f}, lrow[2] = {0.f, 0.f};

    load_kv(0, 0);
    CP_COMMIT();

    for (int kt = 0; kt < SS / 64; kt++) {
        int cur = kt & 1;
        if (kt + 1 < SS / 64) load_kv(cur ^ 1, kt + 1);
        CP_COMMIT();
        CP_WAIT1();
        __syncthreads();

        const __nv_bfloat16* sKh = kvb + cur * KVSTG;
        const __nv_bfloat16* sKl = sKh + 64 * FP;
        const __nv_bfloat16* sVh = sKh + 128 * FP;
        const __nv_bfloat16* sVl = sKh + 192 * FP;

        float s[8][4];
#pragma unroll
        for (int t = 0; t < 8; t++)
#pragma unroll
            for (int v = 0; v < 4; v++) s[t][v] = 0.f;

#pragma unroll
        for (int ks = 0; ks < 4; ks++) {
            uint32_t qhf[4], qlf[4];
            uint32_t qa = (warp * 16 + (lane & 15)) * FP + ks * 16 + (lane >> 4) * 8;
            ldsm_x4(qhf, sptr(sQh + qa));
            ldsm_x4(qlf, sptr(sQl + qa));
#pragma unroll
            for (int np = 0; np < 4; np++) {
                uint32_t kh4[4], kl4[4];
                uint32_t ka = (np * 16 + (lane & 7) + ((lane >> 4) << 3)) * FP
                            + ks * 16 + ((lane >> 3) & 1) * 8;
                ldsm_x4(kh4, sptr(sKh + ka));
                ldsm_x4(kl4, sptr(sKl + ka));
                mma16816(s[2*np],   qhf, &kh4[0]);
                mma16816(s[2*np],   qlf, &kh4[0]);
                mma16816(s[2*np],   qhf, &kl4[0]);
                mma16816(s[2*np+1], qhf, &kh4[2]);
                mma16816(s[2*np+1], qlf, &kh4[2]);
                mma16816(s[2*np+1], qhf, &kl4[2]);
            }
        }

        float mx0 = -1e30f, mx1 = -1e30f;
#pragma unroll
        for (int t = 0; t < 8; t++) {
#pragma unroll
            for (int v = 0; v < 4; v++) s[t][v] *= 0.125f;
            mx0 = fmaxf(mx0, fmaxf(s[t][0], s[t][1]));
            mx1 = fmaxf(mx1, fmaxf(s[t][2], s[t][3]));
        }
#pragma unroll
        for (int off = 1; off <= 2; off <<= 1) {
            mx0 = fmaxf(mx0, __shfl_xor_sync(0xffffffffu, mx0, off));
            mx1 = fmaxf(mx1, __shfl_xor_sync(0xffffffffu, mx1, off));
        }
        float mn0 = fmaxf(mrow[0], mx0), mn1 = fmaxf(mrow[1], mx1);
        float fac0 = __expf(mrow[0] - mn0), fac1 = __expf(mrow[1] - mn1);
        mrow[0] = mn0; mrow[1] = mn1;
        float ls0 = 0.f, ls1 = 0.f;
#pragma unroll
        for (int t = 0; t < 8; t++) {
            s[t][0] = __expf(s[t][0] - mn0); ls0 += s[t][0];
            s[t][1] = __expf(s[t][1] - mn0); ls0 += s[t][1];
            s[t][2] = __expf(s[t][2] - mn1); ls1 += s[t][2];
            s[t][3] = __expf(s[t][3] - mn1); ls1 += s[t][3];
        }
#pragma unroll
        for (int off = 1; off <= 2; off <<= 1) {
            ls0 += __shfl_xor_sync(0xffffffffu, ls0, off);
            ls1 += __shfl_xor_sync(0xffffffffu, ls1, off);
        }
        lrow[0] = lrow[0] * fac0 + ls0;
        lrow[1] = lrow[1] * fac1 + ls1;
#pragma unroll
        for (int t = 0; t < 8; t++) {
            o[t][0] *= fac0; o[t][1] *= fac0;
            o[t][2] *= fac1; o[t][3] *= fac1;
        }

#pragma unroll
        for (int j = 0; j < 4; j++) {
            uint32_t pah[4], pal[4];
            split2(s[2*j][0],   s[2*j][1],   pah[0], pal[0]);
            split2(s[2*j][2],   s[2*j][3],   pah[1], pal[1]);
            split2(s[2*j+1][0], s[2*j+1][1], pah[2], pal[2]);
            split2(s[2*j+1][2], s[2*j+1][3], pah[3], pal[3]);
#pragma unroll
            for (int np = 0; np < 4; np++) {
                uint32_t vh4[4], vl4[4];
                uint32_t va = (j * 16 + (lane & 15)) * FP + np * 16 + (lane >> 4) * 8;
                ldsm_x4t(vh4, sptr(sVh + va));
                ldsm_x4t(vl4, sptr(sVl + va));
                mma16816(o[2*np],   pah, &vh4[0]);
                mma16816(o[2*np],   pal, &vh4[0]);
                mma16816(o[2*np],   pah, &vl4[0]);
                mma16816(o[2*np+1], pah, &vh4[2]);
                mma16816(o[2*np+1], pal, &vh4[2]);
                mma16816(o[2*np+1], pah, &vl4[2]);
            }
        }
        __syncthreads();
    }

    float inv0 = 1.f / lrow[0], inv1 = 1.f / lrow[1];
    int r0 = qbase + warp * 16 + (lane >> 2);
    size_t base0 = (size_t)(b * SS + r0) * NQ + h * DH + (lane & 3) * 2;
    size_t base1 = base0 + (size_t)8 * NQ;
#pragma unroll
    for (int t = 0; t < 8; t++) {
        uint32_t hv, lv;
        split2(o[t][0] * inv0, o[t][1] * inv0, hv, lv);
        *(uint32_t*)&Ch[base0 + t * 8] = hv;
        *(uint32_t*)&Cl[base0 + t * 8] = lv;
        split2(o[t][2] * inv1, o[t][3] * inv1, hv, lv);
        *(uint32_t*)&Ch[base1 + t * 8] = hv;
        *(uint32_t*)&Cl[base1 + t * 8] = lv;
    }
}

// ---------------------------------------------------------------------------
// Launch
// ---------------------------------------------------------------------------
static void split(const float* src, __nv_bfloat16* h, __nv_bfloat16* l, size_t n)
{
    int n4 = (int)(n / 4);
    int blocks = (n4 + 255) / 256;
    if (blocks > 4096) blocks = 4096;
    split_kernel<<<blocks, 256>>>((const float4*)src, (uint2*)h, (uint2*)l, n4);
}

extern "C" void kernel_launch(void* const* d_in, const int* in_sizes, int n_in,
                              void* d_out, int out_size)
{
    const float* x  = (const float*)d_in[0];
    const float* Wq = (const float*)d_in[1];
    const float* Wk = (const float*)d_in[2];
    const float* Wv = (const float*)d_in[3];
    const float* Wo = (const float*)d_in[4];
    float* out = (float*)d_out;

    __nv_bfloat16 *xh, *xl, *Wqh, *Wql, *Wkh, *Wkl, *Wvh, *Wvl, *Woh, *Wol;
    __nv_bfloat16 *Qh, *Ql, *Kh, *Kl, *Vh, *Vl, *Ch, *Cl;
    cudaGetSymbolAddress((void**)&xh,  g_xh);  cudaGetSymbolAddress((void**)&xl,  g_xl);
    cudaGetSymbolAddress((void**)&Wqh, g_Wqh); cudaGetSymbolAddress((void**)&Wql, g_Wql);
    cudaGetSymbolAddress((void**)&Wkh, g_Wkh); cudaGetSymbolAddress((void**)&Wkl, g_Wkl);
    cudaGetSymbolAddress((void**)&Wvh, g_Wvh); cudaGetSymbolAddress((void**)&Wvl, g_Wvl);
    cudaGetSymbolAddress((void**)&Woh, g_Woh); cudaGetSymbolAddress((void**)&Wol, g_Wol);
    cudaGetSymbolAddress((void**)&Qh,  g_Qh);  cudaGetSymbolAddress((void**)&Ql,  g_Ql);
    cudaGetSymbolAddress((void**)&Kh,  g_Kh);  cudaGetSymbolAddress((void**)&Kl,  g_Kl);
    cudaGetSymbolAddress((void**)&Vh,  g_Vh);  cudaGetSymbolAddress((void**)&Vl,  g_Vl);
    cudaGetSymbolAddress((void**)&Ch,  g_Ch);  cudaGetSymbolAddress((void**)&Cl,  g_Cl);

    cudaFuncSetAttribute(qkv_gemm,
                         cudaFuncAttributeMaxDynamicSharedMemorySize, GEMM_SMEM);
    cudaFuncSetAttribute(out_gemm,
                         cudaFuncAttributeMaxDynamicSharedMemorySize, GEMM_SMEM);
    cudaFuncSetAttribute(flash_mma,
                         cudaFuncAttributeMaxDynamicSharedMemorySize, FLASH_SMEM);

    // split inputs
    split(x,  xh,  xl,  (size_t)MROWS * DD);
    split(Wq, Wqh, Wql, (size_t)DD * NQ);
    split(Wk, Wkh, Wkl, (size_t)DD * NKV);
    split(Wv, Wvh, Wvl, (size_t)DD * NKV);
    split(Wo, Woh, Wol, (size_t)NQ * DD);

    // fused Q/K/V projection
    qkv_gemm<<<dim3(24, MROWS / TBM), 256, GEMM_SMEM>>>(
        xh, xl, Wqh, Wql, Wkh, Wkl, Wvh, Wvl, Qh, Ql, Kh, Kl, Vh, Vl);

    // attention
    flash_mma<<<dim3(SS / 128, HQ, BB), 256, FLASH_SMEM>>>(
        Qh, Ql, Kh, Kl, Vh, Vl, Ch, Cl);

    // output projection
    out_gemm<<<dim3(DD / TBN, MROWS / TBM), 256, GEMM_SMEM>>>(
        Ch, Cl, Woh, Wol, out);
}